// round 14
// baseline (speedup 1.0000x reference)
#include <cuda_runtime.h>
#include <cuda_fp16.h>
#include <cuda_bf16.h>
#include <math.h>
#include <stdint.h>

#define BN 128
#define BK 16
#define AST 18   // As row stride (words): gcd(18,32)=2 -> conflict-free pair reads

#define APAD_ROWS 10112   // 79 * 128

// ---------------- scratch (static device globals; no allocation) ----------------
__device__ __align__(256) float g_tmp [10000 * 512];  // h-hat (widest conv = 512)
__device__ __align__(256) float g_h1  [10000 * 128];
__device__ __align__(256) float g_d1  [10000 * 128];
__device__ float g_dis[10016];
__device__ int   g_cnt[10016];
__device__ int   g_rowptr[10017];
__device__ int   g_cursor[10016];
__device__ int   g_eidx[320000];
// fp16 operands for the tensor-core struct GEMM (A split hi/lo, B hi only)
__device__ __align__(256) __half g_ahi[APAD_ROWS * 128];
__device__ __align__(256) __half g_alo[APAD_ROWS * 128];
__device__ __align__(256) __half g_bhi[APAD_ROWS * 128];

// buffer selector: 0 = external pointer, 1..3 = module-global scratch
__device__ __forceinline__ float* sel_buf(int id, float* ext) {
    switch (id) {
        case 1: return g_tmp;
        case 2: return g_h1;
        case 3: return g_d1;
        default: return ext;
    }
}

// packed fp32x2 FMA (full-rate fp32 path on sm_103a; plain FFMA-3reg is half rate)
__device__ __forceinline__ void ffma2(float2 &d, const float2 &a, const float2 &b) {
    unsigned long long du = *reinterpret_cast<unsigned long long*>(&d);
    unsigned long long au = *reinterpret_cast<const unsigned long long*>(&a);
    unsigned long long bu = *reinterpret_cast<const unsigned long long*>(&b);
    asm("fma.rn.f32x2 %0, %1, %2, %0;" : "+l"(du) : "l"(au), "l"(bu));
    d = *reinterpret_cast<float2*>(&du);
}

__device__ __forceinline__ uint32_t smem_to_u32(const void* p) {
    uint32_t a;
    asm("{ .reg .u64 t; cvta.to.shared.u64 t, %1; cvt.u32.u64 %0, t; }" : "=r"(a) : "l"(p));
    return a;
}

__device__ __forceinline__ void cp_async16(uint32_t dst, const void* src) {
    asm volatile("cp.async.cg.shared.global [%0], [%1], 16;" :: "r"(dst), "l"(src));
}

__device__ __forceinline__ void ldsm4(uint32_t* r, uint32_t addr) {
    asm volatile("ldmatrix.sync.aligned.m8n8.x4.shared.b16 {%0,%1,%2,%3}, [%4];"
                 : "=r"(r[0]), "=r"(r[1]), "=r"(r[2]), "=r"(r[3]) : "r"(addr));
}

__device__ __forceinline__ void mma_f16(float* d, const uint32_t* a, const uint32_t* b) {
    asm volatile(
        "mma.sync.aligned.m16n8k16.row.col.f32.f16.f16.f32 "
        "{%0,%1,%2,%3}, {%4,%5,%6,%7}, {%8,%9}, {%0,%1,%2,%3};"
        : "+f"(d[0]), "+f"(d[1]), "+f"(d[2]), "+f"(d[3])
        : "r"(a[0]), "r"(a[1]), "r"(a[2]), "r"(a[3]), "r"(b[0]), "r"(b[1]));
}

// sigmoid(t) = 0.5*tanh(t/2) + 0.5 — single MUFU (tanh.approx) vs EX2+RCP
__device__ __forceinline__ float fast_sigmoid(float t) {
    float th;
    asm("tanh.approx.f32 %0, %1;" : "=f"(th) : "f"(0.5f * t));
    return fmaf(0.5f, th, 0.5f);
}

// ---------------- CSR build ----------------
__global__ void zero_kernel(int N) {
    int i = blockIdx.x * blockDim.x + threadIdx.x;
    if (i < N) g_cnt[i] = 0;
}

__global__ void hist_kernel(const int* __restrict__ dst, int E) {
    int e = blockIdx.x * blockDim.x + threadIdx.x;
    if (e < E) atomicAdd(&g_cnt[dst[e]], 1);
}

__global__ void scan_kernel(int N, int E) {
    __shared__ int sums[256];
    int t = threadIdx.x;
    int chunk = (N + 255) >> 8;
    int b0 = t * chunk;
    int b1 = min(b0 + chunk, N);
    int s = 0;
    for (int i = b0; i < b1; i++) s += g_cnt[i];
    sums[t] = s;
    __syncthreads();
    for (int off = 1; off < 256; off <<= 1) {
        int v = sums[t];
        int w = (t >= off) ? sums[t - off] : 0;
        __syncthreads();
        sums[t] = v + w;
        __syncthreads();
    }
    int pref = (t > 0) ? sums[t - 1] : 0;
    for (int i = b0; i < b1; i++) {
        g_rowptr[i] = pref;
        g_cursor[i] = pref;
        g_dis[i]    = rsqrtf((float)g_cnt[i] + 1.0f);  // deg + self loop
        pref += g_cnt[i];
    }
    if (t == 0) g_rowptr[N] = E;
}

__global__ void fill_kernel(const int* __restrict__ src,
                            const int* __restrict__ dst, int E) {
    int e = blockIdx.x * blockDim.x + threadIdx.x;
    if (e < E) {
        int pos = atomicAdd(&g_cursor[dst[e]], 1);
        g_eidx[pos] = src[e];
    }
}

// zero the padded tail rows of the A (hmid) fp16 operands
__global__ void ztail_kernel(int startRow) {
    int i = blockIdx.x * blockDim.x + threadIdx.x;
    int total = (APAD_ROWS - startRow) * 128;
    if (i < total) {
        __half z = __float2half(0.f);
        g_ahi[(size_t)startRow * 128 + i] = z;
        g_alo[(size_t)startRow * 128 + i] = z;
    }
}

// transpose + fp16 convert Wf[128, Nw] -> g_bhi[n][k] (zero-padded tail)
__global__ void transb_kernel(const float* __restrict__ Wf, int Nw) {
    __shared__ float ts[64 * 129];
    int n0 = blockIdx.x * 64;
    int tid = threadIdx.x;
#pragma unroll
    for (int it = 0; it < 32; it++) {
        int idx = it * 256 + tid;
        int k  = idx >> 6;
        int nl = idx & 63;
        int gn = n0 + nl;
        float v = (gn < Nw) ? Wf[(size_t)k * Nw + gn] : 0.f;
        ts[nl * 129 + k] = v;
    }
    __syncthreads();
#pragma unroll
    for (int it = 0; it < 4; it++) {
        int idx = it * 256 + tid;
        int row = idx >> 4;
        int part = idx & 15;
        __align__(16) __half hi8[8];
#pragma unroll
        for (int j = 0; j < 8; j++)
            hi8[j] = __float2half(ts[row * 129 + part * 8 + j]);
        size_t o = (size_t)(n0 + row) * 128 + part * 8;
        *reinterpret_cast<uint4*>(&g_bhi[o]) = *reinterpret_cast<const uint4*>(hi8);
    }
}

// ---------------- SIMT GEMM: C = epilogue(A[M,K] @ B[K,Nc]) ----------------
// MODE 0: out = (A@B) * dis[row]                 (GCN pre-aggregation)
// MODE 1: out = relu((A@B) + bias[col]); WB: also write fp16 hi/lo to g_ahi/g_alo
// MODE 2: out = sigmoid((A@B) + bias[col])       (fallback path)
template<int MODE, bool SQ, int TM, bool WB>
__global__ __launch_bounds__(256, 1)
void gemm_kernel(const float* __restrict__ Aext, int Aid,
                 const float* __restrict__ B,
                 const float* __restrict__ bias,
                 float* __restrict__ Oext, int Oid,
                 int M, int K, int Nc)
{
    const int BMv = TM * 16;
    const float* A = sel_buf(Aid, const_cast<float*>(Aext));
    float* out = sel_buf(Oid, Oext);

    __shared__ float As[TM * 16 * AST];
    __shared__ float Bs[BK * BN];

    const int tid = threadIdx.x;
    const int tx = tid & 15;
    const int ty = tid >> 4;
    const int row0 = blockIdx.y * BMv;
    const int col0 = blockIdx.x * BN;

    float2 acc[TM][8];
#pragma unroll
    for (int i = 0; i < TM; i++)
#pragma unroll
        for (int j = 0; j < 8; j++) acc[i][j] = make_float2(0.f, 0.f);

    for (int k0 = 0; k0 < K; k0 += BK) {
#pragma unroll
        for (int p = 0; p < TM / 4; p++) {
            int idx = tid + p * 256;
            int r   = idx >> 2;
            int k4  = (idx & 3) << 2;
            float4 v = make_float4(0.f, 0.f, 0.f, 0.f);
            int gr = row0 + r;
            if (gr < M) v = *reinterpret_cast<const float4*>(A + (size_t)gr * K + (k0 + k4));
            if (SQ) { v.x *= v.x; v.y *= v.y; v.z *= v.z; v.w *= v.w; }
            float* d0 = &As[r * AST + k4];
            d0[0] = v.x; d0[1] = v.y; d0[2] = v.z; d0[3] = v.w;
        }
#pragma unroll
        for (int p = 0; p < 2; p++) {
            int idx = tid + p * 256;
            int kr  = idx >> 5;
            int c4  = (idx & 31) << 2;
            float4 v = make_float4(0.f, 0.f, 0.f, 0.f);
            int gc = col0 + c4;
            if (gc < Nc) v = *reinterpret_cast<const float4*>(B + (size_t)(k0 + kr) * Nc + gc);
            *reinterpret_cast<float4*>(&Bs[kr * BN + c4]) = v;
        }
        __syncthreads();

#pragma unroll
        for (int kp = 0; kp < 8; kp++) {
            float2 a2[TM], b2[8];
#pragma unroll
            for (int i = 0; i < TM; i++)
                a2[i] = *reinterpret_cast<const float2*>(&As[(ty + 16 * i) * AST + 2 * kp]);
#pragma unroll
            for (int j = 0; j < 8; j++) {
                b2[j].x = Bs[(2 * kp)     * BN + tx + 16 * j];
                b2[j].y = Bs[(2 * kp + 1) * BN + tx + 16 * j];
            }
#pragma unroll
            for (int i = 0; i < TM; i++)
#pragma unroll
                for (int j = 0; j < 8; j++)
                    ffma2(acc[i][j], a2[i], b2[j]);
        }
        __syncthreads();
    }

    float bv[8];
    if (MODE != 0) {
#pragma unroll
        for (int j = 0; j < 8; j++) {
            int col = col0 + tx + 16 * j;
            bv[j] = (col < Nc) ? bias[col] : 0.f;
        }
    }
#pragma unroll
    for (int i = 0; i < TM; i++) {
        int row = row0 + ty + 16 * i;
        if (row >= M) continue;
        float scale = (MODE == 0) ? g_dis[row] : 1.f;
        size_t roff = (size_t)row * Nc;
#pragma unroll
        for (int j = 0; j < 8; j++) {
            int col = col0 + tx + 16 * j;
            if (col >= Nc) continue;
            float v = acc[i][j].x + acc[i][j].y;
            if (MODE == 0)      v *= scale;
            else if (MODE == 1) v = fmaxf(v + bv[j], 0.f);
            else { float t = v + bv[j]; v = __fdividef(1.f, 1.f + __expf(-t)); }
            if (WB) {
                __half h = __float2half(v);
                g_ahi[roff + col] = h;
                g_alo[roff + col] = __float2half(v - __half2float(h));
            } else {
                out[roff + col] = v;
            }
        }
    }
}

// ---------------- GCN aggregation: atomic-free CSR gather ----------------
// GMODE 0: out = relu(dis*acc + bias)           (standard conv finalize)
// GMODE 1: out = relu(dis*acc + bias) * dis     (conv3: pre-scale for commuted conv4)
// GMODE 2: out = dis*acc                        (conv4 pre-aggregation, no bias/relu)
template<int GMODE>
__global__ void gather_kernel(const float* __restrict__ bias,
                              float* __restrict__ Oext, int Oid, int Iid,
                              int N, int W, int log2wpn)
{
    const float* in = sel_buf(Iid, nullptr);
    float* out = sel_buf(Oid, Oext);
    int gid  = blockIdx.x * blockDim.x + threadIdx.x;
    int gw   = gid >> 5;
    int lane = gid & 31;
    int node = gw >> log2wpn;
    if (node >= N) return;
    int seg = gw & ((1 << log2wpn) - 1);
    int col = (seg << 7) | (lane << 2);

    const float* base = in + col;
    float4 acc = *reinterpret_cast<const float4*>(base + (size_t)node * W);
    int p0 = g_rowptr[node], p1 = g_rowptr[node + 1];
#pragma unroll 4
    for (int p = p0; p < p1; p++) {
        int s = g_eidx[p];
        float4 v = *reinterpret_cast<const float4*>(base + (size_t)s * W);
        acc.x += v.x; acc.y += v.y; acc.z += v.z; acc.w += v.w;
    }
    float d = g_dis[node];
    float4 r;
    if (GMODE == 2) {
        r.x = d * acc.x; r.y = d * acc.y; r.z = d * acc.z; r.w = d * acc.w;
    } else {
        float4 b = *reinterpret_cast<const float4*>(bias + col);
        r.x = fmaxf(fmaf(d, acc.x, b.x), 0.f);
        r.y = fmaxf(fmaf(d, acc.y, b.y), 0.f);
        r.z = fmaxf(fmaf(d, acc.z, b.z), 0.f);
        r.w = fmaxf(fmaf(d, acc.w, b.w), 0.f);
        if (GMODE == 1) { r.x *= d; r.y *= d; r.z *= d; r.w *= d; }
    }
    *reinterpret_cast<float4*>(out + (size_t)node * W + col) = r;
}

// ---------------- struct GEMM: persistent-CTA mma.sync (fp16 2-term split) ------
// out = sigmoid(hmid[M,128] @ Wf[128,Nw] + bf).
// 296 persistent CTAs (2/SM) loop over all 128x128 tiles. The 3-buffer cp.async
// pipeline is seamless ACROSS tiles: at chunk steps 2,3 of tile t, the lookahead
// fetches chunks 0,1 of tile t+gridDim — next-tile loads fly under the current
// tile's HMMAs and epilogue, and wave-transition gaps disappear.
#define SGB 24576            // bytes per buffer slot (3 arrays x 8 KB)
#define SG_BIAS (3 * SGB)
#define SG_SMEM (SG_BIAS + 512)

__device__ __forceinline__ void sg_issue_chunk(
    uint32_t sb, int buf, int c, int tid,
    const char* a0, const char* a1, const char* a2)
{
#pragma unroll
    for (int i = 0; i < 6; i++) {
        int idx = i * 256 + tid;                // 0..1535
        int arr = idx >> 9;                     // 0=AHI, 1=ALO, 2=BHI
        int rem = idx & 511;
        int row = rem >> 2;                     // 0..127
        int q   = rem & 3;                      // 16B unit within 64B row
        int sw  = q ^ ((row >> 1) & 3);
        uint32_t dst = sb + buf * SGB + arr * 8192 + row * 64 + sw * 16;
        const char* base = (arr == 0) ? a0 : (arr == 1) ? a1 : a2;
        cp_async16(dst, base + (size_t)row * 256 + c * 64 + q * 16);
    }
    asm volatile("cp.async.commit_group;" ::: "memory");
}

__global__ __launch_bounds__(256, 2)
void struct_gemm_mma(const float* __restrict__ bf, float* __restrict__ out,
                     int M, int Nw, int ntx, int ntiles)
{
    extern __shared__ __align__(128) char smem[];
    const uint32_t sb = smem_to_u32(smem);
    float* sbias = reinterpret_cast<float*>(smem + SG_BIAS);
    const int tid  = threadIdx.x;
    const int lane = tid & 31;
    const int wid  = tid >> 5;
    const int wm   = wid >> 1;
    const int wn   = wid & 1;

    const int arow = wm * 32 + (lane & 7) + ((lane >> 3) & 1) * 8;
    const int akc  = (lane >> 4) & 1;
    const int brow = wn * 64 + (lane & 7) + ((lane >> 4) & 1) * 8;
    const int bkc  = (lane >> 3) & 1;

    int t0 = blockIdx.x;
    if (t0 >= ntiles) return;

    int row0 = (t0 / ntx) * 128;
    int col0 = (t0 % ntx) * 128;
    const char* a0 = (const char*)g_ahi + (size_t)row0 * 256;
    const char* a1 = (const char*)g_alo + (size_t)row0 * 256;
    const char* a2 = (const char*)g_bhi + (size_t)col0 * 256;

    // prologue: first tile's chunks 0,1
    sg_issue_chunk(sb, 0, 0, tid, a0, a1, a2);
    sg_issue_chunk(sb, 1, 1, tid, a0, a1, a2);

    int base = 0;   // buffer index of current tile's chunk 0
    for (int t = t0; t < ntiles; t += gridDim.x) {
        // bias tile (read only at post-sync acc init; epilogue reads regs only)
        if (tid < 128) {
            int gc = col0 + tid;
            sbias[tid] = (gc < Nw) ? bf[gc] : 0.f;
        }
        const int tnext = t + gridDim.x;
        const bool has_next = (tnext < ntiles);
        int nrow0 = 0, ncol0 = 0;
        const char *n0 = a0, *n1 = a1, *n2 = a2;
        if (has_next) {
            nrow0 = (tnext / ntx) * 128;
            ncol0 = (tnext % ntx) * 128;
            n0 = (const char*)g_ahi + (size_t)nrow0 * 256;
            n1 = (const char*)g_alo + (size_t)nrow0 * 256;
            n2 = (const char*)g_bhi + (size_t)ncol0 * 256;
        }

        float acc[2][8][4];
#pragma unroll
        for (int c = 0; c < 4; c++) {
            if (c < 3 || has_next) asm volatile("cp.async.wait_group 1;" ::: "memory");
            else                   asm volatile("cp.async.wait_group 0;" ::: "memory");
            __syncthreads();
            if (c == 0) {
#pragma unroll
                for (int nt = 0; nt < 8; nt++) {
                    int cl = wn * 64 + nt * 8 + (lane & 3) * 2;
                    float b0 = sbias[cl], b1 = sbias[cl + 1];
#pragma unroll
                    for (int mt = 0; mt < 2; mt++) {
                        acc[mt][nt][0] = b0; acc[mt][nt][1] = b1;
                        acc[mt][nt][2] = b0; acc[mt][nt][3] = b1;
                    }
                }
            }
            // lookahead: chunk c+2 of this tile, or chunk c-2 of the next tile
            int lbuf = (base + c + 2) % 3;
            if (c < 2)          sg_issue_chunk(sb, lbuf, c + 2, tid, a0, a1, a2);
            else if (has_next)  sg_issue_chunk(sb, lbuf, c - 2, tid, n0, n1, n2);

            const uint32_t bb = sb + ((base + c) % 3) * SGB;
#pragma unroll
            for (int ks = 0; ks < 2; ks++) {
                uint32_t ahi[2][4], alo[2][4], bhi[8][2];
#pragma unroll
                for (int mt = 0; mt < 2; mt++) {
                    int r = arow + mt * 16;
                    int sw = (ks * 2 + akc) ^ ((r >> 1) & 3);
                    ldsm4(ahi[mt], bb + 0    + r * 64 + sw * 16);
                    ldsm4(alo[mt], bb + 8192 + r * 64 + sw * 16);
                }
#pragma unroll
                for (int np = 0; np < 4; np++) {
                    int r = brow + np * 16;
                    int sw = (ks * 2 + bkc) ^ ((r >> 1) & 3);
                    uint32_t tt[4];
                    ldsm4(tt, bb + 16384 + r * 64 + sw * 16);
                    bhi[np*2][0] = tt[0]; bhi[np*2][1] = tt[1];
                    bhi[np*2+1][0] = tt[2]; bhi[np*2+1][1] = tt[3];
                }
#pragma unroll
                for (int mt = 0; mt < 2; mt++)
#pragma unroll
                    for (int j = 0; j < 8; j++)
                        mma_f16(acc[mt][j], ahi[mt], bhi[j]);
#pragma unroll
                for (int mt = 0; mt < 2; mt++)
#pragma unroll
                    for (int j = 0; j < 8; j++)
                        mma_f16(acc[mt][j], alo[mt], bhi[j]);
            }
        }

        // epilogue: sigmoid + store (next tile's loads already in flight)
#pragma unroll
        for (int mt = 0; mt < 2; mt++) {
            int rg = row0 + wm * 32 + mt * 16 + (lane >> 2);
#pragma unroll
            for (int nt = 0; nt < 8; nt++) {
                int cl = wn * 64 + nt * 8 + (lane & 3) * 2;
                int cg = col0 + cl;
                if (cg >= Nw) continue;
                const float* a = acc[mt][nt];
                float s0 = fast_sigmoid(a[0]);
                float s1 = fast_sigmoid(a[1]);
                float s2 = fast_sigmoid(a[2]);
                float s3 = fast_sigmoid(a[3]);
                if (rg < M)
                    *reinterpret_cast<float2*>(out + (size_t)rg * Nw + cg) = make_float2(s0, s1);
                if (rg + 8 < M)
                    *reinterpret_cast<float2*>(out + (size_t)(rg + 8) * Nw + cg) = make_float2(s2, s3);
            }
        }

        // advance to next tile
        base = (base + 4) % 3;
        a0 = n0; a1 = n1; a2 = n2;
        row0 = nrow0; col0 = ncol0;
    }
}

// ---------------- launch ----------------
extern "C" void kernel_launch(void* const* d_in, const int* in_sizes, int n_in,
                              void* d_out, int out_size)
{
    const float* x   = (const float*)d_in[0];
    const int*   ei  = (const int*)d_in[1];   // int32 on device (JAX x64 disabled)
    const float* We1 = (const float*)d_in[2];
    const float* be1 = (const float*)d_in[3];
    const float* We2 = (const float*)d_in[4];
    const float* be2 = (const float*)d_in[5];
    const float* Wd1 = (const float*)d_in[6];
    const float* bd1 = (const float*)d_in[7];
    const float* Wd2 = (const float*)d_in[8];
    const float* bd2 = (const float*)d_in[9];
    const float* Wl  = (const float*)d_in[10];
    const float* bl  = (const float*)d_in[11];
    const float* Wf  = (const float*)d_in[12];
    const float* bf  = (const float*)d_in[13];

    const int E = in_sizes[1] / 2;     // edge_index is [2, E]
    const int N = in_sizes[13];        // bf: [N]
    const int F = in_sizes[0] / N;     // x: [N, F]
    const int H = in_sizes[3];         // be1: [H]

    const int* srcp = ei;
    const int* dstp = ei + E;

    float* struct_out = (float*)d_out;                       // [N, N]
    float* xhat_out   = struct_out + (size_t)N * N;          // [N, F]
    float* z_out      = xhat_out + (size_t)N * F;            // [N, H]

    const int tb = 256;
    const bool tc = (H == 128);

    dim3 thr(256);
    auto grid4 = [](int M, int Nc) { return dim3((Nc + BN - 1) / BN, (M + 63) / 64); };
    auto grid8 = [](int M, int Nc) { return dim3((Nc + BN - 1) / BN, (M + 127) / 128); };
    int gb128 = (N * 32 + 255) / 256;       // 1 warp / node  (W = 128)
    int gb512 = (N * 4 * 32 + 255) / 256;   // 4 warps / node (W = 512)

    // CSR (deg/dis) build + struct GEMM prep
    zero_kernel<<<(N + tb - 1) / tb, tb>>>(N);
    if (tc) {
        cudaFuncSetAttribute(struct_gemm_mma, cudaFuncAttributeMaxDynamicSharedMemorySize, SG_SMEM);
        transb_kernel<<<(APAD_ROWS + 63) / 64, 256>>>(Wf, N);
        ztail_kernel<<<((APAD_ROWS - N) * 128 + tb - 1) / tb, tb>>>(N);
    }
    hist_kernel<<<(E + tb - 1) / tb, tb>>>(dstp, E);
    scan_kernel<<<1, 256>>>(N, E);
    fill_kernel<<<(E + tb - 1) / tb, tb>>>(srcp, dstp, E);

    // conv1: x[N,F] @ We1 -> g_tmp -> gather -> g_h1
    gemm_kernel<0, false, 4, false><<<grid4(N, H), thr>>>(x, 0, We1, nullptr, nullptr, 1, N, F, H);
    gather_kernel<0><<<gb128, 256>>>(be1, nullptr, 2, 1, N, H, 0);
    // conv2: g_h1 @ We2 -> g_tmp -> gather -> z (output)
    gemm_kernel<0, false, 4, false><<<grid4(N, H), thr>>>(nullptr, 2, We2, nullptr, nullptr, 1, N, H, H);
    gather_kernel<0><<<gb128, 256>>>(be2, z_out, 0, 1, N, H, 0);
    // conv3: z @ Wd1 -> g_tmp -> gather -> g_d1 (pre-scaled by dis for commuted conv4)
    gemm_kernel<0, false, 4, false><<<grid4(N, H), thr>>>(z_out, 0, Wd1, nullptr, nullptr, 1, N, H, H);

    if (tc) {
        gather_kernel<1><<<gb128, 256>>>(bd1, nullptr, 3, 1, N, H, 0);
        // conv4 (commuted): pre-aggregate d1 (128-wide), then GEMM with fused relu+bias
        gather_kernel<2><<<gb128, 256>>>(nullptr, nullptr, 2, 3, N, H, 0);   // g_d1 -> g_h1
        gemm_kernel<1, false, 4, false><<<grid4(N, F), thr>>>(nullptr, 2, Wd2, bd2, xhat_out, 0, N, H, F);
        // hmid = relu((x_hat^2) @ Wl + bl) -> fp16 hi/lo directly (g_ahi/g_alo)
        gemm_kernel<1, true, 4, true><<<grid4(N, H), thr>>>(xhat_out, 0, Wl, bl, nullptr, 0, N, F, H);
        // struct = sigmoid(hmid @ Wf + bf) — persistent tensor-core GEMM
        int ntx = (N + 127) / 128;
        int ntiles = ntx * ((N + 127) / 128);
        struct_gemm_mma<<<296, thr, SG_SMEM>>>(bf, struct_out, N, N, ntx, ntiles);
    } else {
        // fallback: pure fp32 path, original conv4 order
        gather_kernel<0><<<gb128, 256>>>(bd1, nullptr, 3, 1, N, H, 0);
        gemm_kernel<0, false, 8, false><<<grid8(N, F), thr>>>(nullptr, 3, Wd2, nullptr, nullptr, 1, N, H, F);
        gather_kernel<0><<<gb512, 256>>>(bd2, xhat_out, 0, 1, N, F, 2);
        gemm_kernel<1, true, 4, false><<<grid4(N, H), thr>>>(xhat_out, 0, Wl, bl, nullptr, 1, N, F, H);
        gemm_kernel<2, false, 8, false><<<grid8(N, N), thr>>>(nullptr, 1, Wf, bf, struct_out, 0, N, H, N);
    }
}

// round 15
// speedup vs baseline: 1.1573x; 1.1573x over previous
#include <cuda_runtime.h>
#include <cuda_fp16.h>
#include <cuda_bf16.h>
#include <math.h>
#include <stdint.h>

#define BN 128
#define BK 16
#define AST 18   // As row stride (words): gcd(18,32)=2 -> conflict-free pair reads

#define APAD_ROWS 10112   // 79 * 128

// ---------------- scratch (static device globals; no allocation) ----------------
__device__ __align__(256) float g_tmp [10000 * 512];  // h-hat (widest conv = 512)
__device__ __align__(256) float g_h1  [10000 * 128];
__device__ __align__(256) float g_d1  [10000 * 128];
__device__ float g_dis[10016];
__device__ int   g_cnt[10016];
__device__ int   g_rowptr[10017];
__device__ int   g_cursor[10016];
__device__ int   g_eidx[320000];
// fp16 operands for the tensor-core struct GEMM (A split hi/lo, B hi only)
__device__ __align__(256) __half g_ahi[APAD_ROWS * 128];
__device__ __align__(256) __half g_alo[APAD_ROWS * 128];
__device__ __align__(256) __half g_bhi[APAD_ROWS * 128];

// buffer selector: 0 = external pointer, 1..3 = module-global scratch
__device__ __forceinline__ float* sel_buf(int id, float* ext) {
    switch (id) {
        case 1: return g_tmp;
        case 2: return g_h1;
        case 3: return g_d1;
        default: return ext;
    }
}

// packed fp32x2 FMA (full-rate fp32 path on sm_103a; plain FFMA-3reg is half rate)
__device__ __forceinline__ void ffma2(float2 &d, const float2 &a, const float2 &b) {
    unsigned long long du = *reinterpret_cast<unsigned long long*>(&d);
    unsigned long long au = *reinterpret_cast<const unsigned long long*>(&a);
    unsigned long long bu = *reinterpret_cast<const unsigned long long*>(&b);
    asm("fma.rn.f32x2 %0, %1, %2, %0;" : "+l"(du) : "l"(au), "l"(bu));
    d = *reinterpret_cast<float2*>(&du);
}

__device__ __forceinline__ uint32_t smem_to_u32(const void* p) {
    uint32_t a;
    asm("{ .reg .u64 t; cvta.to.shared.u64 t, %1; cvt.u32.u64 %0, t; }" : "=r"(a) : "l"(p));
    return a;
}

__device__ __forceinline__ void cp_async16(uint32_t dst, const void* src) {
    asm volatile("cp.async.cg.shared.global [%0], [%1], 16;" :: "r"(dst), "l"(src));
}

__device__ __forceinline__ void ldsm4(uint32_t* r, uint32_t addr) {
    asm volatile("ldmatrix.sync.aligned.m8n8.x4.shared.b16 {%0,%1,%2,%3}, [%4];"
                 : "=r"(r[0]), "=r"(r[1]), "=r"(r[2]), "=r"(r[3]) : "r"(addr));
}

__device__ __forceinline__ void mma_f16(float* d, const uint32_t* a, const uint32_t* b) {
    asm volatile(
        "mma.sync.aligned.m16n8k16.row.col.f32.f16.f16.f32 "
        "{%0,%1,%2,%3}, {%4,%5,%6,%7}, {%8,%9}, {%0,%1,%2,%3};"
        : "+f"(d[0]), "+f"(d[1]), "+f"(d[2]), "+f"(d[3])
        : "r"(a[0]), "r"(a[1]), "r"(a[2]), "r"(a[3]), "r"(b[0]), "r"(b[1]));
}

// sigmoid(t) = 0.5*tanh(t/2) + 0.5 — single MUFU (tanh.approx) vs EX2+RCP
__device__ __forceinline__ float fast_sigmoid(float t) {
    float th;
    asm("tanh.approx.f32 %0, %1;" : "=f"(th) : "f"(0.5f * t));
    return fmaf(0.5f, th, 0.5f);
}

// ---------------- CSR build ----------------
__global__ void zero_kernel(int N) {
    int i = blockIdx.x * blockDim.x + threadIdx.x;
    if (i < N) g_cnt[i] = 0;
}

__global__ void hist_kernel(const int* __restrict__ dst, int E) {
    int e = blockIdx.x * blockDim.x + threadIdx.x;
    if (e < E) atomicAdd(&g_cnt[dst[e]], 1);
}

__global__ void scan_kernel(int N, int E) {
    __shared__ int sums[256];
    int t = threadIdx.x;
    int chunk = (N + 255) >> 8;
    int b0 = t * chunk;
    int b1 = min(b0 + chunk, N);
    int s = 0;
    for (int i = b0; i < b1; i++) s += g_cnt[i];
    sums[t] = s;
    __syncthreads();
    for (int off = 1; off < 256; off <<= 1) {
        int v = sums[t];
        int w = (t >= off) ? sums[t - off] : 0;
        __syncthreads();
        sums[t] = v + w;
        __syncthreads();
    }
    int pref = (t > 0) ? sums[t - 1] : 0;
    for (int i = b0; i < b1; i++) {
        g_rowptr[i] = pref;
        g_cursor[i] = pref;
        g_dis[i]    = rsqrtf((float)g_cnt[i] + 1.0f);  // deg + self loop
        pref += g_cnt[i];
    }
    if (t == 0) g_rowptr[N] = E;
}

__global__ void fill_kernel(const int* __restrict__ src,
                            const int* __restrict__ dst, int E) {
    int e = blockIdx.x * blockDim.x + threadIdx.x;
    if (e < E) {
        int pos = atomicAdd(&g_cursor[dst[e]], 1);
        g_eidx[pos] = src[e];
    }
}

// zero the padded tail rows of the A (hmid) fp16 operands
__global__ void ztail_kernel(int startRow) {
    int i = blockIdx.x * blockDim.x + threadIdx.x;
    int total = (APAD_ROWS - startRow) * 128;
    if (i < total) {
        __half z = __float2half(0.f);
        g_ahi[(size_t)startRow * 128 + i] = z;
        g_alo[(size_t)startRow * 128 + i] = z;
    }
}

// transpose + fp16 convert Wf[128, Nw] -> g_bhi[n][k] (zero-padded tail)
__global__ void transb_kernel(const float* __restrict__ Wf, int Nw) {
    __shared__ float ts[64 * 129];
    int n0 = blockIdx.x * 64;
    int tid = threadIdx.x;
#pragma unroll
    for (int it = 0; it < 32; it++) {
        int idx = it * 256 + tid;
        int k  = idx >> 6;
        int nl = idx & 63;
        int gn = n0 + nl;
        float v = (gn < Nw) ? Wf[(size_t)k * Nw + gn] : 0.f;
        ts[nl * 129 + k] = v;
    }
    __syncthreads();
#pragma unroll
    for (int it = 0; it < 4; it++) {
        int idx = it * 256 + tid;
        int row = idx >> 4;
        int part = idx & 15;
        __align__(16) __half hi8[8];
#pragma unroll
        for (int j = 0; j < 8; j++)
            hi8[j] = __float2half(ts[row * 129 + part * 8 + j]);
        size_t o = (size_t)(n0 + row) * 128 + part * 8;
        *reinterpret_cast<uint4*>(&g_bhi[o]) = *reinterpret_cast<const uint4*>(hi8);
    }
}

// ---------------- SIMT GEMM: C = epilogue(A[M,K] @ B[K,Nc]) ----------------
// MODE 0: out = (A@B) * dis[row]                 (GCN pre-aggregation)
// MODE 1: out = relu((A@B) + bias[col]); WB: also write fp16 hi/lo to g_ahi/g_alo
// MODE 2: out = sigmoid((A@B) + bias[col])       (fallback path)
template<int MODE, bool SQ, int TM, bool WB>
__global__ __launch_bounds__(256, (TM <= 4) ? 2 : 1)
void gemm_kernel(const float* __restrict__ Aext, int Aid,
                 const float* __restrict__ B,
                 const float* __restrict__ bias,
                 float* __restrict__ Oext, int Oid,
                 int M, int K, int Nc)
{
    const int BMv = TM * 16;
    const float* A = sel_buf(Aid, const_cast<float*>(Aext));
    float* out = sel_buf(Oid, Oext);

    __shared__ float As[TM * 16 * AST];
    __shared__ float Bs[BK * BN];

    const int tid = threadIdx.x;
    const int tx = tid & 15;
    const int ty = tid >> 4;
    const int row0 = blockIdx.y * BMv;
    const int col0 = blockIdx.x * BN;

    float2 acc[TM][8];
#pragma unroll
    for (int i = 0; i < TM; i++)
#pragma unroll
        for (int j = 0; j < 8; j++) acc[i][j] = make_float2(0.f, 0.f);

    for (int k0 = 0; k0 < K; k0 += BK) {
#pragma unroll
        for (int p = 0; p < TM / 4; p++) {
            int idx = tid + p * 256;
            int r   = idx >> 2;
            int k4  = (idx & 3) << 2;
            float4 v = make_float4(0.f, 0.f, 0.f, 0.f);
            int gr = row0 + r;
            if (gr < M) v = *reinterpret_cast<const float4*>(A + (size_t)gr * K + (k0 + k4));
            if (SQ) { v.x *= v.x; v.y *= v.y; v.z *= v.z; v.w *= v.w; }
            float* d0 = &As[r * AST + k4];
            d0[0] = v.x; d0[1] = v.y; d0[2] = v.z; d0[3] = v.w;
        }
#pragma unroll
        for (int p = 0; p < 2; p++) {
            int idx = tid + p * 256;
            int kr  = idx >> 5;
            int c4  = (idx & 31) << 2;
            float4 v = make_float4(0.f, 0.f, 0.f, 0.f);
            int gc = col0 + c4;
            if (gc < Nc) v = *reinterpret_cast<const float4*>(B + (size_t)(k0 + kr) * Nc + gc);
            *reinterpret_cast<float4*>(&Bs[kr * BN + c4]) = v;
        }
        __syncthreads();

#pragma unroll
        for (int kp = 0; kp < 8; kp++) {
            float2 a2[TM], b2[8];
#pragma unroll
            for (int i = 0; i < TM; i++)
                a2[i] = *reinterpret_cast<const float2*>(&As[(ty + 16 * i) * AST + 2 * kp]);
#pragma unroll
            for (int j = 0; j < 8; j++) {
                b2[j].x = Bs[(2 * kp)     * BN + tx + 16 * j];
                b2[j].y = Bs[(2 * kp + 1) * BN + tx + 16 * j];
            }
#pragma unroll
            for (int i = 0; i < TM; i++)
#pragma unroll
                for (int j = 0; j < 8; j++)
                    ffma2(acc[i][j], a2[i], b2[j]);
        }
        __syncthreads();
    }

    float bv[8];
    if (MODE != 0) {
#pragma unroll
        for (int j = 0; j < 8; j++) {
            int col = col0 + tx + 16 * j;
            bv[j] = (col < Nc) ? bias[col] : 0.f;
        }
    }
#pragma unroll
    for (int i = 0; i < TM; i++) {
        int row = row0 + ty + 16 * i;
        if (row >= M) continue;
        float scale = (MODE == 0) ? g_dis[row] : 1.f;
        size_t roff = (size_t)row * Nc;
#pragma unroll
        for (int j = 0; j < 8; j++) {
            int col = col0 + tx + 16 * j;
            if (col >= Nc) continue;
            float v = acc[i][j].x + acc[i][j].y;
            if (MODE == 0)      v *= scale;
            else if (MODE == 1) v = fmaxf(v + bv[j], 0.f);
            else { float t = v + bv[j]; v = __fdividef(1.f, 1.f + __expf(-t)); }
            if (WB) {
                __half h = __float2half(v);
                g_ahi[roff + col] = h;
                g_alo[roff + col] = __float2half(v - __half2float(h));
            } else {
                out[roff + col] = v;
            }
        }
    }
}

// ---------------- GCN aggregation: atomic-free CSR gather ----------------
// GMODE 0: out = relu(dis*acc + bias)           (standard conv finalize)
// GMODE 1: out = relu(dis*acc + bias) * dis     (conv3: pre-scale for commuted conv4)
// GMODE 2: out = dis*acc                        (conv4 pre-aggregation, no bias/relu)
template<int GMODE>
__global__ void gather_kernel(const float* __restrict__ bias,
                              float* __restrict__ Oext, int Oid, int Iid,
                              int N, int W, int log2wpn)
{
    const float* in = sel_buf(Iid, nullptr);
    float* out = sel_buf(Oid, Oext);
    int gid  = blockIdx.x * blockDim.x + threadIdx.x;
    int gw   = gid >> 5;
    int lane = gid & 31;
    int node = gw >> log2wpn;
    if (node >= N) return;
    int seg = gw & ((1 << log2wpn) - 1);
    int col = (seg << 7) | (lane << 2);

    const float* base = in + col;
    float4 acc = *reinterpret_cast<const float4*>(base + (size_t)node * W);
    int p0 = g_rowptr[node], p1 = g_rowptr[node + 1];
#pragma unroll 4
    for (int p = p0; p < p1; p++) {
        int s = g_eidx[p];
        float4 v = *reinterpret_cast<const float4*>(base + (size_t)s * W);
        acc.x += v.x; acc.y += v.y; acc.z += v.z; acc.w += v.w;
    }
    float d = g_dis[node];
    float4 r;
    if (GMODE == 2) {
        r.x = d * acc.x; r.y = d * acc.y; r.z = d * acc.z; r.w = d * acc.w;
    } else {
        float4 b = *reinterpret_cast<const float4*>(bias + col);
        r.x = fmaxf(fmaf(d, acc.x, b.x), 0.f);
        r.y = fmaxf(fmaf(d, acc.y, b.y), 0.f);
        r.z = fmaxf(fmaf(d, acc.z, b.z), 0.f);
        r.w = fmaxf(fmaf(d, acc.w, b.w), 0.f);
        if (GMODE == 1) { r.x *= d; r.y *= d; r.z *= d; r.w *= d; }
    }
    *reinterpret_cast<float4*>(out + (size_t)node * W + col) = r;
}

// ---------------- struct GEMM via mma.sync (fp16 2-term split, fp32 accum) ------
// out = sigmoid(hmid[M,128] @ Wf[128,Nw] + bf).
// A = ahi + alo (fp16 pair), B = bhi (fp16). D += ahi*bhi + alo*bhi; the dropped
// ahi*blo term is ~2^-11 relative — far under the 1e-3 budget.
// CTA tile 128x128; K in 4 chunks of 32; three-buffer cp.async pipeline, one
// __syncthreads per chunk; 2 CTAs/SM; term passes of 16 independent HMMAs.
#define SGB 24576            // bytes per buffer slot (3 arrays x 8 KB)
#define SG_BIAS (3 * SGB)
#define SG_SMEM (SG_BIAS + 512)

__device__ __forceinline__ void sg_issue_chunk(
    uint32_t sb, int buf, int c, int tid,
    const char* a0, const char* a1, const char* a2)
{
#pragma unroll
    for (int i = 0; i < 6; i++) {
        int idx = i * 256 + tid;                // 0..1535
        int arr = idx >> 9;                     // 0=AHI, 1=ALO, 2=BHI
        int rem = idx & 511;
        int row = rem >> 2;                     // 0..127
        int q   = rem & 3;                      // 16B unit within 64B row
        int sw  = q ^ ((row >> 1) & 3);
        uint32_t dst = sb + buf * SGB + arr * 8192 + row * 64 + sw * 16;
        const char* base = (arr == 0) ? a0 : (arr == 1) ? a1 : a2;
        cp_async16(dst, base + (size_t)row * 256 + c * 64 + q * 16);
    }
    asm volatile("cp.async.commit_group;" ::: "memory");
}

__global__ __launch_bounds__(256, 2)
void struct_gemm_mma(const float* __restrict__ bf, float* __restrict__ out,
                     int M, int Nw)
{
    extern __shared__ __align__(128) char smem[];
    const uint32_t sb = smem_to_u32(smem);
    const int tid  = threadIdx.x;
    const int lane = tid & 31;
    const int wid  = tid >> 5;
    const int wm   = wid >> 1;
    const int wn   = wid & 1;
    const int row0 = blockIdx.y * 128;
    const int col0 = blockIdx.x * 128;

    if (tid < 128) {
        int gc = col0 + tid;
        *reinterpret_cast<float*>(smem + SG_BIAS + tid * 4) = (gc < Nw) ? bf[gc] : 0.f;
    }

    const char* a0 = (const char*)g_ahi + (size_t)row0 * 256;
    const char* a1 = (const char*)g_alo + (size_t)row0 * 256;
    const char* a2 = (const char*)g_bhi + (size_t)col0 * 256;

    sg_issue_chunk(sb, 0, 0, tid, a0, a1, a2);
    sg_issue_chunk(sb, 1, 1, tid, a0, a1, a2);

    float acc[2][8][4];

    const int arow = wm * 32 + (lane & 7) + ((lane >> 3) & 1) * 8;
    const int akc  = (lane >> 4) & 1;
    const int brow = wn * 64 + (lane & 7) + ((lane >> 4) & 1) * 8;
    const int bkc  = (lane >> 3) & 1;

#pragma unroll
    for (int c = 0; c < 4; c++) {
        if (c < 3) asm volatile("cp.async.wait_group 1;" ::: "memory");
        else       asm volatile("cp.async.wait_group 0;" ::: "memory");
        __syncthreads();   // single barrier per chunk (3-buffer rotation)
        if (c == 0) {
            const float* sbias = reinterpret_cast<const float*>(smem + SG_BIAS);
#pragma unroll
            for (int nt = 0; nt < 8; nt++) {
                int cl = wn * 64 + nt * 8 + (lane & 3) * 2;
                float b0 = sbias[cl], b1 = sbias[cl + 1];
#pragma unroll
                for (int mt = 0; mt < 2; mt++) {
                    acc[mt][nt][0] = b0; acc[mt][nt][1] = b1;
                    acc[mt][nt][2] = b0; acc[mt][nt][3] = b1;
                }
            }
        }
        // prefetch chunk c+2 into buffer (c+2)%3 — flies under this chunk's HMMAs
        if (c < 2) sg_issue_chunk(sb, (c + 2) % 3, c + 2, tid, a0, a1, a2);

        const uint32_t bb = sb + (c % 3) * SGB;
#pragma unroll
        for (int ks = 0; ks < 2; ks++) {
            uint32_t ahi[2][4], alo[2][4], bhi[8][2];
#pragma unroll
            for (int mt = 0; mt < 2; mt++) {
                int r = arow + mt * 16;
                int sw = (ks * 2 + akc) ^ ((r >> 1) & 3);
                ldsm4(ahi[mt], bb + 0    + r * 64 + sw * 16);
                ldsm4(alo[mt], bb + 8192 + r * 64 + sw * 16);
            }
#pragma unroll
            for (int np = 0; np < 4; np++) {
                int r = brow + np * 16;
                int sw = (ks * 2 + bkc) ^ ((r >> 1) & 3);
                uint32_t t[4];
                ldsm4(t, bb + 16384 + r * 64 + sw * 16);
                bhi[np*2][0] = t[0]; bhi[np*2][1] = t[1];
                bhi[np*2+1][0] = t[2]; bhi[np*2+1][1] = t[3];
            }
            // 2 term passes, 16 independent HMMAs each
#pragma unroll
            for (int mt = 0; mt < 2; mt++)
#pragma unroll
                for (int j = 0; j < 8; j++)
                    mma_f16(acc[mt][j], ahi[mt], bhi[j]);
#pragma unroll
            for (int mt = 0; mt < 2; mt++)
#pragma unroll
                for (int j = 0; j < 8; j++)
                    mma_f16(acc[mt][j], alo[mt], bhi[j]);
        }
    }

    // epilogue: sigmoid + store (bias already folded into acc)
#pragma unroll
    for (int mt = 0; mt < 2; mt++) {
        int rg = row0 + wm * 32 + mt * 16 + (lane >> 2);
#pragma unroll
        for (int nt = 0; nt < 8; nt++) {
            int cl = wn * 64 + nt * 8 + (lane & 3) * 2;
            int cg = col0 + cl;
            if (cg >= Nw) continue;
            const float* a = acc[mt][nt];
            float s0 = fast_sigmoid(a[0]);
            float s1 = fast_sigmoid(a[1]);
            float s2 = fast_sigmoid(a[2]);
            float s3 = fast_sigmoid(a[3]);
            if (rg < M)
                *reinterpret_cast<float2*>(out + (size_t)rg * Nw + cg) = make_float2(s0, s1);
            if (rg + 8 < M)
                *reinterpret_cast<float2*>(out + (size_t)(rg + 8) * Nw + cg) = make_float2(s2, s3);
        }
    }
}

// ---------------- launch ----------------
extern "C" void kernel_launch(void* const* d_in, const int* in_sizes, int n_in,
                              void* d_out, int out_size)
{
    const float* x   = (const float*)d_in[0];
    const int*   ei  = (const int*)d_in[1];   // int32 on device (JAX x64 disabled)
    const float* We1 = (const float*)d_in[2];
    const float* be1 = (const float*)d_in[3];
    const float* We2 = (const float*)d_in[4];
    const float* be2 = (const float*)d_in[5];
    const float* Wd1 = (const float*)d_in[6];
    const float* bd1 = (const float*)d_in[7];
    const float* Wd2 = (const float*)d_in[8];
    const float* bd2 = (const float*)d_in[9];
    const float* Wl  = (const float*)d_in[10];
    const float* bl  = (const float*)d_in[11];
    const float* Wf  = (const float*)d_in[12];
    const float* bf  = (const float*)d_in[13];

    const int E = in_sizes[1] / 2;     // edge_index is [2, E]
    const int N = in_sizes[13];        // bf: [N]
    const int F = in_sizes[0] / N;     // x: [N, F]
    const int H = in_sizes[3];         // be1: [H]

    const int* srcp = ei;
    const int* dstp = ei + E;

    float* struct_out = (float*)d_out;                       // [N, N]
    float* xhat_out   = struct_out + (size_t)N * N;          // [N, F]
    float* z_out      = xhat_out + (size_t)N * F;            // [N, H]

    const int tb = 256;
    const bool tc = (H == 128);

    dim3 thr(256);
    auto grid4 = [](int M, int Nc) { return dim3((Nc + BN - 1) / BN, (M + 63) / 64); };
    auto grid8 = [](int M, int Nc) { return dim3((Nc + BN - 1) / BN, (M + 127) / 128); };
    int gb128 = (N * 32 + 255) / 256;       // 1 warp / node  (W = 128)
    int gb512 = (N * 4 * 32 + 255) / 256;   // 4 warps / node (W = 512)

    // CSR (deg/dis) build + struct GEMM prep
    zero_kernel<<<(N + tb - 1) / tb, tb>>>(N);
    if (tc) {
        cudaFuncSetAttribute(struct_gemm_mma, cudaFuncAttributeMaxDynamicSharedMemorySize, SG_SMEM);
        transb_kernel<<<(APAD_ROWS + 63) / 64, 256>>>(Wf, N);
        ztail_kernel<<<((APAD_ROWS - N) * 128 + tb - 1) / tb, tb>>>(N);
    }
    hist_kernel<<<(E + tb - 1) / tb, tb>>>(dstp, E);
    scan_kernel<<<1, 256>>>(N, E);
    fill_kernel<<<(E + tb - 1) / tb, tb>>>(srcp, dstp, E);

    // conv1: x[N,F] @ We1 -> g_tmp -> gather -> g_h1
    gemm_kernel<0, false, 4, false><<<grid4(N, H), thr>>>(x, 0, We1, nullptr, nullptr, 1, N, F, H);
    gather_kernel<0><<<gb128, 256>>>(be1, nullptr, 2, 1, N, H, 0);
    // conv2: g_h1 @ We2 -> g_tmp -> gather -> z (output)
    gemm_kernel<0, false, 4, false><<<grid4(N, H), thr>>>(nullptr, 2, We2, nullptr, nullptr, 1, N, H, H);
    gather_kernel<0><<<gb128, 256>>>(be2, z_out, 0, 1, N, H, 0);
    // conv3: z @ Wd1 -> g_tmp -> gather -> g_d1 (pre-scaled by dis for commuted conv4)
    gemm_kernel<0, false, 4, false><<<grid4(N, H), thr>>>(z_out, 0, Wd1, nullptr, nullptr, 1, N, H, H);

    if (tc) {
        gather_kernel<1><<<gb128, 256>>>(bd1, nullptr, 3, 1, N, H, 0);
        // conv4 (commuted): pre-aggregate d1 (128-wide), then GEMM with fused relu+bias
        gather_kernel<2><<<gb128, 256>>>(nullptr, nullptr, 2, 3, N, H, 0);   // g_d1 -> g_h1
        gemm_kernel<1, false, 4, false><<<grid4(N, F), thr>>>(nullptr, 2, Wd2, bd2, xhat_out, 0, N, H, F);
        // hmid = relu((x_hat^2) @ Wl + bl) -> fp16 hi/lo directly (g_ahi/g_alo)
        gemm_kernel<1, true, 4, true><<<grid4(N, H), thr>>>(xhat_out, 0, Wl, bl, nullptr, 0, N, F, H);
        // struct = sigmoid(hmid @ Wf + bf) via tensor cores (fp16 2-term split)
        dim3 gs((N + 127) / 128, (N + 127) / 128);
        struct_gemm_mma<<<gs, thr, SG_SMEM>>>(bf, struct_out, N, N);
    } else {
        // fallback: pure fp32 path, original conv4 order
        gather_kernel<0><<<gb128, 256>>>(bd1, nullptr, 3, 1, N, H, 0);
        gemm_kernel<0, false, 8, false><<<grid8(N, F), thr>>>(nullptr, 3, Wd2, nullptr, nullptr, 1, N, H, F);
        gather_kernel<0><<<gb512, 256>>>(bd2, xhat_out, 0, 1, N, F, 2);
        gemm_kernel<1, true, 4, false><<<grid4(N, H), thr>>>(xhat_out, 0, Wl, bl, nullptr, 1, N, F, H);
        gemm_kernel<2, false, 8, false><<<grid8(N, N), thr>>>(nullptr, 1, Wf, bf, struct_out, 0, N, H, N);
    }
}

// round 16
// speedup vs baseline: 1.1585x; 1.0010x over previous
#include <cuda_runtime.h>
#include <cuda_fp16.h>
#include <cuda_bf16.h>
#include <math.h>
#include <stdint.h>

#define BN 128
#define BK 16
#define AST 18   // As row stride (words): gcd(18,32)=2 -> conflict-free pair reads

#define APAD_ROWS 10112   // 79 * 128

// ---------------- scratch (static device globals; no allocation) ----------------
__device__ __align__(256) float g_tmp [10000 * 512];  // h-hat (widest conv = 512)
__device__ __align__(256) float g_h1  [10000 * 128];
__device__ __align__(256) float g_d1  [10000 * 128];
__device__ float g_dis[10016];
__device__ int   g_cnt[10016];
__device__ int   g_rowptr[10017];
__device__ int   g_cursor[10016];
__device__ int   g_eidx[320000];
// fp16 operands for the tensor-core struct GEMM (A split hi/lo, B hi only)
__device__ __align__(256) __half g_ahi[APAD_ROWS * 128];
__device__ __align__(256) __half g_alo[APAD_ROWS * 128];
__device__ __align__(256) __half g_bhi[APAD_ROWS * 128];

// buffer selector: 0 = external pointer, 1..3 = module-global scratch
__device__ __forceinline__ float* sel_buf(int id, float* ext) {
    switch (id) {
        case 1: return g_tmp;
        case 2: return g_h1;
        case 3: return g_d1;
        default: return ext;
    }
}

// packed fp32x2 FMA (full-rate fp32 path on sm_103a; plain FFMA-3reg is half rate)
__device__ __forceinline__ void ffma2(float2 &d, const float2 &a, const float2 &b) {
    unsigned long long du = *reinterpret_cast<unsigned long long*>(&d);
    unsigned long long au = *reinterpret_cast<const unsigned long long*>(&a);
    unsigned long long bu = *reinterpret_cast<const unsigned long long*>(&b);
    asm("fma.rn.f32x2 %0, %1, %2, %0;" : "+l"(du) : "l"(au), "l"(bu));
    d = *reinterpret_cast<float2*>(&du);
}

__device__ __forceinline__ uint32_t smem_to_u32(const void* p) {
    uint32_t a;
    asm("{ .reg .u64 t; cvta.to.shared.u64 t, %1; cvt.u32.u64 %0, t; }" : "=r"(a) : "l"(p));
    return a;
}

__device__ __forceinline__ void cp_async16(uint32_t dst, const void* src) {
    asm volatile("cp.async.cg.shared.global [%0], [%1], 16;" :: "r"(dst), "l"(src));
}

__device__ __forceinline__ void ldsm4(uint32_t* r, uint32_t addr) {
    asm volatile("ldmatrix.sync.aligned.m8n8.x4.shared.b16 {%0,%1,%2,%3}, [%4];"
                 : "=r"(r[0]), "=r"(r[1]), "=r"(r[2]), "=r"(r[3]) : "r"(addr));
}

__device__ __forceinline__ void mma_f16(float* d, const uint32_t* a, const uint32_t* b) {
    asm volatile(
        "mma.sync.aligned.m16n8k16.row.col.f32.f16.f16.f32 "
        "{%0,%1,%2,%3}, {%4,%5,%6,%7}, {%8,%9}, {%0,%1,%2,%3};"
        : "+f"(d[0]), "+f"(d[1]), "+f"(d[2]), "+f"(d[3])
        : "r"(a[0]), "r"(a[1]), "r"(a[2]), "r"(a[3]), "r"(b[0]), "r"(b[1]));
}

// scalar sigmoid via f32 tanh (used by fallback path)
__device__ __forceinline__ float fast_sigmoid(float t) {
    float th;
    asm("tanh.approx.f32 %0, %1;" : "=f"(th) : "f"(0.5f * t));
    return fmaf(0.5f, th, 0.5f);
}

// paired sigmoid: 1 MUFU (tanh.approx.f16x2) for TWO elements.
// sigma(t) = 0.5*tanh(t/2) + 0.5, computed in f16x2 (abs err ~3e-4 worst-case,
// norm rel_err ~1e-4 — well under the 1e-3 budget).
__device__ __forceinline__ float2 fast_sigmoid2(float t0, float t1) {
    __half2 h = __floats2half2_rn(0.5f * t0, 0.5f * t1);
    uint32_t u = *reinterpret_cast<uint32_t*>(&h);
    asm("tanh.approx.f16x2 %0, %0;" : "+r"(u));
    __half2 th = *reinterpret_cast<__half2*>(&u);
    __half2 s = __hfma2(th, __float2half2_rn(0.5f), __float2half2_rn(0.5f));
    return __half22float2(s);
}

// ---------------- CSR build ----------------
__global__ void zero_kernel(int N) {
    int i = blockIdx.x * blockDim.x + threadIdx.x;
    if (i < N) g_cnt[i] = 0;
}

__global__ void hist_kernel(const int* __restrict__ dst, int E) {
    int e = blockIdx.x * blockDim.x + threadIdx.x;
    if (e < E) atomicAdd(&g_cnt[dst[e]], 1);
}

__global__ void scan_kernel(int N, int E) {
    __shared__ int sums[256];
    int t = threadIdx.x;
    int chunk = (N + 255) >> 8;
    int b0 = t * chunk;
    int b1 = min(b0 + chunk, N);
    int s = 0;
    for (int i = b0; i < b1; i++) s += g_cnt[i];
    sums[t] = s;
    __syncthreads();
    for (int off = 1; off < 256; off <<= 1) {
        int v = sums[t];
        int w = (t >= off) ? sums[t - off] : 0;
        __syncthreads();
        sums[t] = v + w;
        __syncthreads();
    }
    int pref = (t > 0) ? sums[t - 1] : 0;
    for (int i = b0; i < b1; i++) {
        g_rowptr[i] = pref;
        g_cursor[i] = pref;
        g_dis[i]    = rsqrtf((float)g_cnt[i] + 1.0f);  // deg + self loop
        pref += g_cnt[i];
    }
    if (t == 0) g_rowptr[N] = E;
}

__global__ void fill_kernel(const int* __restrict__ src,
                            const int* __restrict__ dst, int E) {
    int e = blockIdx.x * blockDim.x + threadIdx.x;
    if (e < E) {
        int pos = atomicAdd(&g_cursor[dst[e]], 1);
        g_eidx[pos] = src[e];
    }
}

// zero the padded tail rows of the A (hmid) fp16 operands
__global__ void ztail_kernel(int startRow) {
    int i = blockIdx.x * blockDim.x + threadIdx.x;
    int total = (APAD_ROWS - startRow) * 128;
    if (i < total) {
        __half z = __float2half(0.f);
        g_ahi[(size_t)startRow * 128 + i] = z;
        g_alo[(size_t)startRow * 128 + i] = z;
    }
}

// transpose + fp16 convert Wf[128, Nw] -> g_bhi[n][k] (zero-padded tail)
__global__ void transb_kernel(const float* __restrict__ Wf, int Nw) {
    __shared__ float ts[64 * 129];
    int n0 = blockIdx.x * 64;
    int tid = threadIdx.x;
#pragma unroll
    for (int it = 0; it < 32; it++) {
        int idx = it * 256 + tid;
        int k  = idx >> 6;
        int nl = idx & 63;
        int gn = n0 + nl;
        float v = (gn < Nw) ? Wf[(size_t)k * Nw + gn] : 0.f;
        ts[nl * 129 + k] = v;
    }
    __syncthreads();
#pragma unroll
    for (int it = 0; it < 4; it++) {
        int idx = it * 256 + tid;
        int row = idx >> 4;
        int part = idx & 15;
        __align__(16) __half hi8[8];
#pragma unroll
        for (int j = 0; j < 8; j++)
            hi8[j] = __float2half(ts[row * 129 + part * 8 + j]);
        size_t o = (size_t)(n0 + row) * 128 + part * 8;
        *reinterpret_cast<uint4*>(&g_bhi[o]) = *reinterpret_cast<const uint4*>(hi8);
    }
}

// ---------------- SIMT GEMM: C = epilogue(A[M,K] @ B[K,Nc]) ----------------
// MODE 0: out = (A@B) * dis[row]                 (GCN pre-aggregation)
// MODE 1: out = relu((A@B) + bias[col]); WB: also write fp16 hi/lo to g_ahi/g_alo
// MODE 2: out = sigmoid((A@B) + bias[col])       (fallback path)
template<int MODE, bool SQ, int TM, bool WB>
__global__ __launch_bounds__(256, (TM <= 4) ? 2 : 1)
void gemm_kernel(const float* __restrict__ Aext, int Aid,
                 const float* __restrict__ B,
                 const float* __restrict__ bias,
                 float* __restrict__ Oext, int Oid,
                 int M, int K, int Nc)
{
    const int BMv = TM * 16;
    const float* A = sel_buf(Aid, const_cast<float*>(Aext));
    float* out = sel_buf(Oid, Oext);

    __shared__ float As[TM * 16 * AST];
    __shared__ float Bs[BK * BN];

    const int tid = threadIdx.x;
    const int tx = tid & 15;
    const int ty = tid >> 4;
    const int row0 = blockIdx.y * BMv;
    const int col0 = blockIdx.x * BN;

    float2 acc[TM][8];
#pragma unroll
    for (int i = 0; i < TM; i++)
#pragma unroll
        for (int j = 0; j < 8; j++) acc[i][j] = make_float2(0.f, 0.f);

    for (int k0 = 0; k0 < K; k0 += BK) {
#pragma unroll
        for (int p = 0; p < TM / 4; p++) {
            int idx = tid + p * 256;
            int r   = idx >> 2;
            int k4  = (idx & 3) << 2;
            float4 v = make_float4(0.f, 0.f, 0.f, 0.f);
            int gr = row0 + r;
            if (gr < M) v = *reinterpret_cast<const float4*>(A + (size_t)gr * K + (k0 + k4));
            if (SQ) { v.x *= v.x; v.y *= v.y; v.z *= v.z; v.w *= v.w; }
            float* d0 = &As[r * AST + k4];
            d0[0] = v.x; d0[1] = v.y; d0[2] = v.z; d0[3] = v.w;
        }
#pragma unroll
        for (int p = 0; p < 2; p++) {
            int idx = tid + p * 256;
            int kr  = idx >> 5;
            int c4  = (idx & 31) << 2;
            float4 v = make_float4(0.f, 0.f, 0.f, 0.f);
            int gc = col0 + c4;
            if (gc < Nc) v = *reinterpret_cast<const float4*>(B + (size_t)(k0 + kr) * Nc + gc);
            *reinterpret_cast<float4*>(&Bs[kr * BN + c4]) = v;
        }
        __syncthreads();

#pragma unroll
        for (int kp = 0; kp < 8; kp++) {
            float2 a2[TM], b2[8];
#pragma unroll
            for (int i = 0; i < TM; i++)
                a2[i] = *reinterpret_cast<const float2*>(&As[(ty + 16 * i) * AST + 2 * kp]);
#pragma unroll
            for (int j = 0; j < 8; j++) {
                b2[j].x = Bs[(2 * kp)     * BN + tx + 16 * j];
                b2[j].y = Bs[(2 * kp + 1) * BN + tx + 16 * j];
            }
#pragma unroll
            for (int i = 0; i < TM; i++)
#pragma unroll
                for (int j = 0; j < 8; j++)
                    ffma2(acc[i][j], a2[i], b2[j]);
        }
        __syncthreads();
    }

    float bv[8];
    if (MODE != 0) {
#pragma unroll
        for (int j = 0; j < 8; j++) {
            int col = col0 + tx + 16 * j;
            bv[j] = (col < Nc) ? bias[col] : 0.f;
        }
    }
#pragma unroll
    for (int i = 0; i < TM; i++) {
        int row = row0 + ty + 16 * i;
        if (row >= M) continue;
        float scale = (MODE == 0) ? g_dis[row] : 1.f;
        size_t roff = (size_t)row * Nc;
#pragma unroll
        for (int j = 0; j < 8; j++) {
            int col = col0 + tx + 16 * j;
            if (col >= Nc) continue;
            float v = acc[i][j].x + acc[i][j].y;
            if (MODE == 0)      v *= scale;
            else if (MODE == 1) v = fmaxf(v + bv[j], 0.f);
            else { float t = v + bv[j]; v = __fdividef(1.f, 1.f + __expf(-t)); }
            if (WB) {
                __half h = __float2half(v);
                g_ahi[roff + col] = h;
                g_alo[roff + col] = __float2half(v - __half2float(h));
            } else {
                out[roff + col] = v;
            }
        }
    }
}

// ---------------- GCN aggregation: atomic-free CSR gather ----------------
// GMODE 0: out = relu(dis*acc + bias)           (standard conv finalize)
// GMODE 1: out = relu(dis*acc + bias) * dis     (conv3: pre-scale for commuted conv4)
// GMODE 2: out = dis*acc                        (conv4 pre-aggregation, no bias/relu)
template<int GMODE>
__global__ void gather_kernel(const float* __restrict__ bias,
                              float* __restrict__ Oext, int Oid, int Iid,
                              int N, int W, int log2wpn)
{
    const float* in = sel_buf(Iid, nullptr);
    float* out = sel_buf(Oid, Oext);
    int gid  = blockIdx.x * blockDim.x + threadIdx.x;
    int gw   = gid >> 5;
    int lane = gid & 31;
    int node = gw >> log2wpn;
    if (node >= N) return;
    int seg = gw & ((1 << log2wpn) - 1);
    int col = (seg << 7) | (lane << 2);

    const float* base = in + col;
    float4 acc = *reinterpret_cast<const float4*>(base + (size_t)node * W);
    int p0 = g_rowptr[node], p1 = g_rowptr[node + 1];
#pragma unroll 4
    for (int p = p0; p < p1; p++) {
        int s = g_eidx[p];
        float4 v = *reinterpret_cast<const float4*>(base + (size_t)s * W);
        acc.x += v.x; acc.y += v.y; acc.z += v.z; acc.w += v.w;
    }
    float d = g_dis[node];
    float4 r;
    if (GMODE == 2) {
        r.x = d * acc.x; r.y = d * acc.y; r.z = d * acc.z; r.w = d * acc.w;
    } else {
        float4 b = *reinterpret_cast<const float4*>(bias + col);
        r.x = fmaxf(fmaf(d, acc.x, b.x), 0.f);
        r.y = fmaxf(fmaf(d, acc.y, b.y), 0.f);
        r.z = fmaxf(fmaf(d, acc.z, b.z), 0.f);
        r.w = fmaxf(fmaf(d, acc.w, b.w), 0.f);
        if (GMODE == 1) { r.x *= d; r.y *= d; r.z *= d; r.w *= d; }
    }
    *reinterpret_cast<float4*>(out + (size_t)node * W + col) = r;
}

// ---------------- struct GEMM via mma.sync (fp16 2-term split, fp32 accum) ------
// out = sigmoid(hmid[M,128] @ Wf[128,Nw] + bf).
// A = ahi + alo (fp16 pair), B = bhi (fp16). D += ahi*bhi + alo*bhi.
// CTA tile 128x128; K in 4 chunks of 32; three-buffer cp.async pipeline, one
// __syncthreads per chunk; 2 CTAs/SM; sigmoid epilogue via tanh.approx.f16x2
// (one MUFU per TWO outputs — the epilogue MUFU stream is the current bound).
#define SGB 24576            // bytes per buffer slot (3 arrays x 8 KB)
#define SG_BIAS (3 * SGB)
#define SG_SMEM (SG_BIAS + 512)

__device__ __forceinline__ void sg_issue_chunk(
    uint32_t sb, int buf, int c, int tid,
    const char* a0, const char* a1, const char* a2)
{
#pragma unroll
    for (int i = 0; i < 6; i++) {
        int idx = i * 256 + tid;                // 0..1535
        int arr = idx >> 9;                     // 0=AHI, 1=ALO, 2=BHI
        int rem = idx & 511;
        int row = rem >> 2;                     // 0..127
        int q   = rem & 3;                      // 16B unit within 64B row
        int sw  = q ^ ((row >> 1) & 3);
        uint32_t dst = sb + buf * SGB + arr * 8192 + row * 64 + sw * 16;
        const char* base = (arr == 0) ? a0 : (arr == 1) ? a1 : a2;
        cp_async16(dst, base + (size_t)row * 256 + c * 64 + q * 16);
    }
    asm volatile("cp.async.commit_group;" ::: "memory");
}

__global__ __launch_bounds__(256, 2)
void struct_gemm_mma(const float* __restrict__ bf, float* __restrict__ out,
                     int M, int Nw)
{
    extern __shared__ __align__(128) char smem[];
    const uint32_t sb = smem_to_u32(smem);
    const int tid  = threadIdx.x;
    const int lane = tid & 31;
    const int wid  = tid >> 5;
    const int wm   = wid >> 1;
    const int wn   = wid & 1;
    const int row0 = blockIdx.y * 128;
    const int col0 = blockIdx.x * 128;

    if (tid < 128) {
        int gc = col0 + tid;
        *reinterpret_cast<float*>(smem + SG_BIAS + tid * 4) = (gc < Nw) ? bf[gc] : 0.f;
    }

    const char* a0 = (const char*)g_ahi + (size_t)row0 * 256;
    const char* a1 = (const char*)g_alo + (size_t)row0 * 256;
    const char* a2 = (const char*)g_bhi + (size_t)col0 * 256;

    sg_issue_chunk(sb, 0, 0, tid, a0, a1, a2);
    sg_issue_chunk(sb, 1, 1, tid, a0, a1, a2);

    float acc[2][8][4];

    const int arow = wm * 32 + (lane & 7) + ((lane >> 3) & 1) * 8;
    const int akc  = (lane >> 4) & 1;
    const int brow = wn * 64 + (lane & 7) + ((lane >> 4) & 1) * 8;
    const int bkc  = (lane >> 3) & 1;

#pragma unroll
    for (int c = 0; c < 4; c++) {
        if (c < 3) asm volatile("cp.async.wait_group 1;" ::: "memory");
        else       asm volatile("cp.async.wait_group 0;" ::: "memory");
        __syncthreads();   // single barrier per chunk (3-buffer rotation)
        if (c == 0) {
            const float* sbias = reinterpret_cast<const float*>(smem + SG_BIAS);
#pragma unroll
            for (int nt = 0; nt < 8; nt++) {
                int cl = wn * 64 + nt * 8 + (lane & 3) * 2;
                float b0 = sbias[cl], b1 = sbias[cl + 1];
#pragma unroll
                for (int mt = 0; mt < 2; mt++) {
                    acc[mt][nt][0] = b0; acc[mt][nt][1] = b1;
                    acc[mt][nt][2] = b0; acc[mt][nt][3] = b1;
                }
            }
        }
        // prefetch chunk c+2 into buffer (c+2)%3 — flies under this chunk's HMMAs
        if (c < 2) sg_issue_chunk(sb, (c + 2) % 3, c + 2, tid, a0, a1, a2);

        const uint32_t bb = sb + (c % 3) * SGB;
#pragma unroll
        for (int ks = 0; ks < 2; ks++) {
            uint32_t ahi[2][4], alo[2][4], bhi[8][2];
#pragma unroll
            for (int mt = 0; mt < 2; mt++) {
                int r = arow + mt * 16;
                int sw = (ks * 2 + akc) ^ ((r >> 1) & 3);
                ldsm4(ahi[mt], bb + 0    + r * 64 + sw * 16);
                ldsm4(alo[mt], bb + 8192 + r * 64 + sw * 16);
            }
#pragma unroll
            for (int np = 0; np < 4; np++) {
                int r = brow + np * 16;
                int sw = (ks * 2 + bkc) ^ ((r >> 1) & 3);
                uint32_t t[4];
                ldsm4(t, bb + 16384 + r * 64 + sw * 16);
                bhi[np*2][0] = t[0]; bhi[np*2][1] = t[1];
                bhi[np*2+1][0] = t[2]; bhi[np*2+1][1] = t[3];
            }
            // 2 term passes, 16 independent HMMAs each
#pragma unroll
            for (int mt = 0; mt < 2; mt++)
#pragma unroll
                for (int j = 0; j < 8; j++)
                    mma_f16(acc[mt][j], ahi[mt], bhi[j]);
#pragma unroll
            for (int mt = 0; mt < 2; mt++)
#pragma unroll
                for (int j = 0; j < 8; j++)
                    mma_f16(acc[mt][j], alo[mt], bhi[j]);
        }
    }

    // epilogue: paired f16x2 sigmoid + store (bias already folded into acc)
#pragma unroll
    for (int mt = 0; mt < 2; mt++) {
        int rg = row0 + wm * 32 + mt * 16 + (lane >> 2);
#pragma unroll
        for (int nt = 0; nt < 8; nt++) {
            int cl = wn * 64 + nt * 8 + (lane & 3) * 2;
            int cg = col0 + cl;
            if (cg >= Nw) continue;
            const float* a = acc[mt][nt];
            float2 s01 = fast_sigmoid2(a[0], a[1]);
            float2 s23 = fast_sigmoid2(a[2], a[3]);
            if (rg < M)
                *reinterpret_cast<float2*>(out + (size_t)rg * Nw + cg) = s01;
            if (rg + 8 < M)
                *reinterpret_cast<float2*>(out + (size_t)(rg + 8) * Nw + cg) = s23;
        }
    }
}

// ---------------- launch ----------------
extern "C" void kernel_launch(void* const* d_in, const int* in_sizes, int n_in,
                              void* d_out, int out_size)
{
    const float* x   = (const float*)d_in[0];
    const int*   ei  = (const int*)d_in[1];   // int32 on device (JAX x64 disabled)
    const float* We1 = (const float*)d_in[2];
    const float* be1 = (const float*)d_in[3];
    const float* We2 = (const float*)d_in[4];
    const float* be2 = (const float*)d_in[5];
    const float* Wd1 = (const float*)d_in[6];
    const float* bd1 = (const float*)d_in[7];
    const float* Wd2 = (const float*)d_in[8];
    const float* bd2 = (const float*)d_in[9];
    const float* Wl  = (const float*)d_in[10];
    const float* bl  = (const float*)d_in[11];
    const float* Wf  = (const float*)d_in[12];
    const float* bf  = (const float*)d_in[13];

    const int E = in_sizes[1] / 2;     // edge_index is [2, E]
    const int N = in_sizes[13];        // bf: [N]
    const int F = in_sizes[0] / N;     // x: [N, F]
    const int H = in_sizes[3];         // be1: [H]

    const int* srcp = ei;
    const int* dstp = ei + E;

    float* struct_out = (float*)d_out;                       // [N, N]
    float* xhat_out   = struct_out + (size_t)N * N;          // [N, F]
    float* z_out      = xhat_out + (size_t)N * F;            // [N, H]

    const int tb = 256;
    const bool tc = (H == 128);

    dim3 thr(256);
    auto grid4 = [](int M, int Nc) { return dim3((Nc + BN - 1) / BN, (M + 63) / 64); };
    auto grid8 = [](int M, int Nc) { return dim3((Nc + BN - 1) / BN, (M + 127) / 128); };
    int gb128 = (N * 32 + 255) / 256;       // 1 warp / node  (W = 128)
    int gb512 = (N * 4 * 32 + 255) / 256;   // 4 warps / node (W = 512)

    // CSR (deg/dis) build + struct GEMM prep
    zero_kernel<<<(N + tb - 1) / tb, tb>>>(N);
    if (tc) {
        cudaFuncSetAttribute(struct_gemm_mma, cudaFuncAttributeMaxDynamicSharedMemorySize, SG_SMEM);
        transb_kernel<<<(APAD_ROWS + 63) / 64, 256>>>(Wf, N);
        ztail_kernel<<<((APAD_ROWS - N) * 128 + tb - 1) / tb, tb>>>(N);
    }
    hist_kernel<<<(E + tb - 1) / tb, tb>>>(dstp, E);
    scan_kernel<<<1, 256>>>(N, E);
    fill_kernel<<<(E + tb - 1) / tb, tb>>>(srcp, dstp, E);

    // conv1: x[N,F] @ We1 -> g_tmp -> gather -> g_h1
    gemm_kernel<0, false, 4, false><<<grid4(N, H), thr>>>(x, 0, We1, nullptr, nullptr, 1, N, F, H);
    gather_kernel<0><<<gb128, 256>>>(be1, nullptr, 2, 1, N, H, 0);
    // conv2: g_h1 @ We2 -> g_tmp -> gather -> z (output)
    gemm_kernel<0, false, 4, false><<<grid4(N, H), thr>>>(nullptr, 2, We2, nullptr, nullptr, 1, N, H, H);
    gather_kernel<0><<<gb128, 256>>>(be2, z_out, 0, 1, N, H, 0);
    // conv3: z @ Wd1 -> g_tmp -> gather -> g_d1 (pre-scaled by dis for commuted conv4)
    gemm_kernel<0, false, 4, false><<<grid4(N, H), thr>>>(z_out, 0, Wd1, nullptr, nullptr, 1, N, H, H);

    if (tc) {
        gather_kernel<1><<<gb128, 256>>>(bd1, nullptr, 3, 1, N, H, 0);
        // conv4 (commuted): pre-aggregate d1 (128-wide), then GEMM with fused relu+bias
        gather_kernel<2><<<gb128, 256>>>(nullptr, nullptr, 2, 3, N, H, 0);   // g_d1 -> g_h1
        gemm_kernel<1, false, 4, false><<<grid4(N, F), thr>>>(nullptr, 2, Wd2, bd2, xhat_out, 0, N, H, F);
        // hmid = relu((x_hat^2) @ Wl + bl) -> fp16 hi/lo directly (g_ahi/g_alo)
        gemm_kernel<1, true, 4, true><<<grid4(N, H), thr>>>(xhat_out, 0, Wl, bl, nullptr, 0, N, F, H);
        // struct = sigmoid(hmid @ Wf + bf) via tensor cores (fp16 2-term split)
        dim3 gs((N + 127) / 128, (N + 127) / 128);
        struct_gemm_mma<<<gs, thr, SG_SMEM>>>(bf, struct_out, N, N);
    } else {
        // fallback: pure fp32 path, original conv4 order
        gather_kernel<0><<<gb128, 256>>>(bd1, nullptr, 3, 1, N, H, 0);
        gemm_kernel<0, false, 8, false><<<grid8(N, F), thr>>>(nullptr, 3, Wd2, nullptr, nullptr, 1, N, H, F);
        gather_kernel<0><<<gb512, 256>>>(bd2, xhat_out, 0, 1, N, F, 2);
        gemm_kernel<1, true, 4, false><<<grid4(N, H), thr>>>(xhat_out, 0, Wl, bl, nullptr, 1, N, F, H);
        gemm_kernel<2, false, 8, false><<<grid8(N, N), thr>>>(nullptr, 1, Wf, bf, struct_out, 0, N, H, N);
    }
}

// round 17
// speedup vs baseline: 1.1804x; 1.0189x over previous
#include <cuda_runtime.h>
#include <cuda_fp16.h>
#include <cuda_bf16.h>
#include <math.h>
#include <stdint.h>

#define BN 128
#define BK 16
#define AST 18   // As row stride (words): gcd(18,32)=2 -> conflict-free pair reads

#define APAD_ROWS 10112   // 79 * 128

// ---------------- scratch (static device globals; no allocation) ----------------
__device__ __align__(256) float g_tmp [10000 * 512];  // h-hat (widest conv = 512)
__device__ __align__(256) float g_h1  [10000 * 128];
__device__ __align__(256) float g_d1  [10000 * 128];
__device__ float g_dis[10016];
__device__ int   g_cnt[10016];
__device__ int   g_rowptr[10017];
__device__ int   g_cursor[10016];
__device__ int   g_eidx[320000];
// fp16 operands for the tensor-core struct GEMM (A split hi/lo, B hi only)
__device__ __align__(256) __half g_ahi[APAD_ROWS * 128];
__device__ __align__(256) __half g_alo[APAD_ROWS * 128];
__device__ __align__(256) __half g_bhi[APAD_ROWS * 128];

// buffer selector: 0 = external pointer, 1..3 = module-global scratch
__device__ __forceinline__ float* sel_buf(int id, float* ext) {
    switch (id) {
        case 1: return g_tmp;
        case 2: return g_h1;
        case 3: return g_d1;
        default: return ext;
    }
}

// packed fp32x2 FMA (full-rate fp32 path on sm_103a; plain FFMA-3reg is half rate)
__device__ __forceinline__ void ffma2(float2 &d, const float2 &a, const float2 &b) {
    unsigned long long du = *reinterpret_cast<unsigned long long*>(&d);
    unsigned long long au = *reinterpret_cast<const unsigned long long*>(&a);
    unsigned long long bu = *reinterpret_cast<const unsigned long long*>(&b);
    asm("fma.rn.f32x2 %0, %1, %2, %0;" : "+l"(du) : "l"(au), "l"(bu));
    d = *reinterpret_cast<float2*>(&du);
}

__device__ __forceinline__ uint32_t smem_to_u32(const void* p) {
    uint32_t a;
    asm("{ .reg .u64 t; cvta.to.shared.u64 t, %1; cvt.u32.u64 %0, t; }" : "=r"(a) : "l"(p));
    return a;
}

__device__ __forceinline__ void cp_async16(uint32_t dst, const void* src) {
    asm volatile("cp.async.cg.shared.global [%0], [%1], 16;" :: "r"(dst), "l"(src));
}

__device__ __forceinline__ void ldsm4(uint32_t* r, uint32_t addr) {
    asm volatile("ldmatrix.sync.aligned.m8n8.x4.shared.b16 {%0,%1,%2,%3}, [%4];"
                 : "=r"(r[0]), "=r"(r[1]), "=r"(r[2]), "=r"(r[3]) : "r"(addr));
}

__device__ __forceinline__ void mma_f16(float* d, const uint32_t* a, const uint32_t* b) {
    asm volatile(
        "mma.sync.aligned.m16n8k16.row.col.f32.f16.f16.f32 "
        "{%0,%1,%2,%3}, {%4,%5,%6,%7}, {%8,%9}, {%0,%1,%2,%3};"
        : "+f"(d[0]), "+f"(d[1]), "+f"(d[2]), "+f"(d[3])
        : "r"(a[0]), "r"(a[1]), "r"(a[2]), "r"(a[3]), "r"(b[0]), "r"(b[1]));
}

// sigmoid(t) = 0.5*tanh(t/2) + 0.5 — single f32 MUFU (tanh.approx)
__device__ __forceinline__ float fast_sigmoid(float t) {
    float th;
    asm("tanh.approx.f32 %0, %1;" : "=f"(th) : "f"(0.5f * t));
    return fmaf(0.5f, th, 0.5f);
}

// streaming store (evict-first): output is written once, never re-read
__device__ __forceinline__ void stg_cs_v2(float* p, float a, float b) {
    asm volatile("st.global.cs.v2.f32 [%0], {%1, %2};" :: "l"(p), "f"(a), "f"(b) : "memory");
}

// ---------------- CSR build ----------------
__global__ void zero_kernel(int N) {
    int i = blockIdx.x * blockDim.x + threadIdx.x;
    if (i < N) g_cnt[i] = 0;
}

__global__ void hist_kernel(const int* __restrict__ dst, int E) {
    int e = blockIdx.x * blockDim.x + threadIdx.x;
    if (e < E) atomicAdd(&g_cnt[dst[e]], 1);
}

__global__ void scan_kernel(int N, int E) {
    __shared__ int sums[256];
    int t = threadIdx.x;
    int chunk = (N + 255) >> 8;
    int b0 = t * chunk;
    int b1 = min(b0 + chunk, N);
    int s = 0;
    for (int i = b0; i < b1; i++) s += g_cnt[i];
    sums[t] = s;
    __syncthreads();
    for (int off = 1; off < 256; off <<= 1) {
        int v = sums[t];
        int w = (t >= off) ? sums[t - off] : 0;
        __syncthreads();
        sums[t] = v + w;
        __syncthreads();
    }
    int pref = (t > 0) ? sums[t - 1] : 0;
    for (int i = b0; i < b1; i++) {
        g_rowptr[i] = pref;
        g_cursor[i] = pref;
        g_dis[i]    = rsqrtf((float)g_cnt[i] + 1.0f);  // deg + self loop
        pref += g_cnt[i];
    }
    if (t == 0) g_rowptr[N] = E;
}

__global__ void fill_kernel(const int* __restrict__ src,
                            const int* __restrict__ dst, int E) {
    int e = blockIdx.x * blockDim.x + threadIdx.x;
    if (e < E) {
        int pos = atomicAdd(&g_cursor[dst[e]], 1);
        g_eidx[pos] = src[e];
    }
}

// zero the padded tail rows of the A (hmid) fp16 operands
__global__ void ztail_kernel(int startRow) {
    int i = blockIdx.x * blockDim.x + threadIdx.x;
    int total = (APAD_ROWS - startRow) * 128;
    if (i < total) {
        __half z = __float2half(0.f);
        g_ahi[(size_t)startRow * 128 + i] = z;
        g_alo[(size_t)startRow * 128 + i] = z;
    }
}

// transpose + fp16 convert Wf[128, Nw] -> g_bhi[n][k] (zero-padded tail)
__global__ void transb_kernel(const float* __restrict__ Wf, int Nw) {
    __shared__ float ts[64 * 129];
    int n0 = blockIdx.x * 64;
    int tid = threadIdx.x;
#pragma unroll
    for (int it = 0; it < 32; it++) {
        int idx = it * 256 + tid;
        int k  = idx >> 6;
        int nl = idx & 63;
        int gn = n0 + nl;
        float v = (gn < Nw) ? Wf[(size_t)k * Nw + gn] : 0.f;
        ts[nl * 129 + k] = v;
    }
    __syncthreads();
#pragma unroll
    for (int it = 0; it < 4; it++) {
        int idx = it * 256 + tid;
        int row = idx >> 4;
        int part = idx & 15;
        __align__(16) __half hi8[8];
#pragma unroll
        for (int j = 0; j < 8; j++)
            hi8[j] = __float2half(ts[row * 129 + part * 8 + j]);
        size_t o = (size_t)(n0 + row) * 128 + part * 8;
        *reinterpret_cast<uint4*>(&g_bhi[o]) = *reinterpret_cast<const uint4*>(hi8);
    }
}

// ---------------- SIMT GEMM: C = epilogue(A[M,K] @ B[K,Nc]) ----------------
// MODE 0: out = (A@B) * dis[row]                 (GCN pre-aggregation)
// MODE 1: out = relu((A@B) + bias[col]); WB: also write fp16 hi/lo to g_ahi/g_alo
// MODE 2: out = sigmoid((A@B) + bias[col])       (fallback path)
template<int MODE, bool SQ, int TM, bool WB>
__global__ __launch_bounds__(256, (TM <= 4) ? 2 : 1)
void gemm_kernel(const float* __restrict__ Aext, int Aid,
                 const float* __restrict__ B,
                 const float* __restrict__ bias,
                 float* __restrict__ Oext, int Oid,
                 int M, int K, int Nc)
{
    const int BMv = TM * 16;
    const float* A = sel_buf(Aid, const_cast<float*>(Aext));
    float* out = sel_buf(Oid, Oext);

    __shared__ float As[TM * 16 * AST];
    __shared__ float Bs[BK * BN];

    const int tid = threadIdx.x;
    const int tx = tid & 15;
    const int ty = tid >> 4;
    const int row0 = blockIdx.y * BMv;
    const int col0 = blockIdx.x * BN;

    float2 acc[TM][8];
#pragma unroll
    for (int i = 0; i < TM; i++)
#pragma unroll
        for (int j = 0; j < 8; j++) acc[i][j] = make_float2(0.f, 0.f);

    for (int k0 = 0; k0 < K; k0 += BK) {
#pragma unroll
        for (int p = 0; p < TM / 4; p++) {
            int idx = tid + p * 256;
            int r   = idx >> 2;
            int k4  = (idx & 3) << 2;
            float4 v = make_float4(0.f, 0.f, 0.f, 0.f);
            int gr = row0 + r;
            if (gr < M) v = *reinterpret_cast<const float4*>(A + (size_t)gr * K + (k0 + k4));
            if (SQ) { v.x *= v.x; v.y *= v.y; v.z *= v.z; v.w *= v.w; }
            float* d0 = &As[r * AST + k4];
            d0[0] = v.x; d0[1] = v.y; d0[2] = v.z; d0[3] = v.w;
        }
#pragma unroll
        for (int p = 0; p < 2; p++) {
            int idx = tid + p * 256;
            int kr  = idx >> 5;
            int c4  = (idx & 31) << 2;
            float4 v = make_float4(0.f, 0.f, 0.f, 0.f);
            int gc = col0 + c4;
            if (gc < Nc) v = *reinterpret_cast<const float4*>(B + (size_t)(k0 + kr) * Nc + gc);
            *reinterpret_cast<float4*>(&Bs[kr * BN + c4]) = v;
        }
        __syncthreads();

#pragma unroll
        for (int kp = 0; kp < 8; kp++) {
            float2 a2[TM], b2[8];
#pragma unroll
            for (int i = 0; i < TM; i++)
                a2[i] = *reinterpret_cast<const float2*>(&As[(ty + 16 * i) * AST + 2 * kp]);
#pragma unroll
            for (int j = 0; j < 8; j++) {
                b2[j].x = Bs[(2 * kp)     * BN + tx + 16 * j];
                b2[j].y = Bs[(2 * kp + 1) * BN + tx + 16 * j];
            }
#pragma unroll
            for (int i = 0; i < TM; i++)
#pragma unroll
                for (int j = 0; j < 8; j++)
                    ffma2(acc[i][j], a2[i], b2[j]);
        }
        __syncthreads();
    }

    float bv[8];
    if (MODE != 0) {
#pragma unroll
        for (int j = 0; j < 8; j++) {
            int col = col0 + tx + 16 * j;
            bv[j] = (col < Nc) ? bias[col] : 0.f;
        }
    }
#pragma unroll
    for (int i = 0; i < TM; i++) {
        int row = row0 + ty + 16 * i;
        if (row >= M) continue;
        float scale = (MODE == 0) ? g_dis[row] : 1.f;
        size_t roff = (size_t)row * Nc;
#pragma unroll
        for (int j = 0; j < 8; j++) {
            int col = col0 + tx + 16 * j;
            if (col >= Nc) continue;
            float v = acc[i][j].x + acc[i][j].y;
            if (MODE == 0)      v *= scale;
            else if (MODE == 1) v = fmaxf(v + bv[j], 0.f);
            else { float t = v + bv[j]; v = __fdividef(1.f, 1.f + __expf(-t)); }
            if (WB) {
                __half h = __float2half(v);
                g_ahi[roff + col] = h;
                g_alo[roff + col] = __float2half(v - __half2float(h));
            } else {
                out[roff + col] = v;
            }
        }
    }
}

// ---------------- GCN aggregation: atomic-free CSR gather ----------------
// GMODE 0: out = relu(dis*acc + bias)           (standard conv finalize)
// GMODE 1: out = relu(dis*acc + bias) * dis     (conv3: pre-scale for commuted conv4)
// GMODE 2: out = dis*acc                        (conv4 pre-aggregation, no bias/relu)
template<int GMODE>
__global__ void gather_kernel(const float* __restrict__ bias,
                              float* __restrict__ Oext, int Oid, int Iid,
                              int N, int W, int log2wpn)
{
    const float* in = sel_buf(Iid, nullptr);
    float* out = sel_buf(Oid, Oext);
    int gid  = blockIdx.x * blockDim.x + threadIdx.x;
    int gw   = gid >> 5;
    int lane = gid & 31;
    int node = gw >> log2wpn;
    if (node >= N) return;
    int seg = gw & ((1 << log2wpn) - 1);
    int col = (seg << 7) | (lane << 2);

    const float* base = in + col;
    float4 acc = *reinterpret_cast<const float4*>(base + (size_t)node * W);
    int p0 = g_rowptr[node], p1 = g_rowptr[node + 1];
#pragma unroll 4
    for (int p = p0; p < p1; p++) {
        int s = g_eidx[p];
        float4 v = *reinterpret_cast<const float4*>(base + (size_t)s * W);
        acc.x += v.x; acc.y += v.y; acc.z += v.z; acc.w += v.w;
    }
    float d = g_dis[node];
    float4 r;
    if (GMODE == 2) {
        r.x = d * acc.x; r.y = d * acc.y; r.z = d * acc.z; r.w = d * acc.w;
    } else {
        float4 b = *reinterpret_cast<const float4*>(bias + col);
        r.x = fmaxf(fmaf(d, acc.x, b.x), 0.f);
        r.y = fmaxf(fmaf(d, acc.y, b.y), 0.f);
        r.z = fmaxf(fmaf(d, acc.z, b.z), 0.f);
        r.w = fmaxf(fmaf(d, acc.w, b.w), 0.f);
        if (GMODE == 1) { r.x *= d; r.y *= d; r.z *= d; r.w *= d; }
    }
    *reinterpret_cast<float4*>(out + (size_t)node * W + col) = r;
}

// ---------------- struct GEMM via mma.sync (fp16 2-term split, fp32 accum) ------
// out = sigmoid(hmid[M,128] @ Wf[128,Nw] + bf).
// A = ahi + alo (fp16 pair), B = bhi (fp16). D += ahi*bhi + alo*bhi.
// CTA tile 128x128; K in 4 chunks of 32; three-buffer cp.async pipeline, one
// __syncthreads per chunk; 2 CTAs/SM; f32 tanh sigmoid epilogue; streaming
// stores (.cs) so the 400 MB one-shot output doesn't thrash the L2-resident
// fp16 operand arrays.
#define SGB 24576            // bytes per buffer slot (3 arrays x 8 KB)
#define SG_BIAS (3 * SGB)
#define SG_SMEM (SG_BIAS + 512)

__device__ __forceinline__ void sg_issue_chunk(
    uint32_t sb, int buf, int c, int tid,
    const char* a0, const char* a1, const char* a2)
{
#pragma unroll
    for (int i = 0; i < 6; i++) {
        int idx = i * 256 + tid;                // 0..1535
        int arr = idx >> 9;                     // 0=AHI, 1=ALO, 2=BHI
        int rem = idx & 511;
        int row = rem >> 2;                     // 0..127
        int q   = rem & 3;                      // 16B unit within 64B row
        int sw  = q ^ ((row >> 1) & 3);
        uint32_t dst = sb + buf * SGB + arr * 8192 + row * 64 + sw * 16;
        const char* base = (arr == 0) ? a0 : (arr == 1) ? a1 : a2;
        cp_async16(dst, base + (size_t)row * 256 + c * 64 + q * 16);
    }
    asm volatile("cp.async.commit_group;" ::: "memory");
}

__global__ __launch_bounds__(256, 2)
void struct_gemm_mma(const float* __restrict__ bf, float* __restrict__ out,
                     int M, int Nw)
{
    extern __shared__ __align__(128) char smem[];
    const uint32_t sb = smem_to_u32(smem);
    const int tid  = threadIdx.x;
    const int lane = tid & 31;
    const int wid  = tid >> 5;
    const int wm   = wid >> 1;
    const int wn   = wid & 1;
    const int row0 = blockIdx.y * 128;
    const int col0 = blockIdx.x * 128;

    if (tid < 128) {
        int gc = col0 + tid;
        *reinterpret_cast<float*>(smem + SG_BIAS + tid * 4) = (gc < Nw) ? bf[gc] : 0.f;
    }

    const char* a0 = (const char*)g_ahi + (size_t)row0 * 256;
    const char* a1 = (const char*)g_alo + (size_t)row0 * 256;
    const char* a2 = (const char*)g_bhi + (size_t)col0 * 256;

    sg_issue_chunk(sb, 0, 0, tid, a0, a1, a2);
    sg_issue_chunk(sb, 1, 1, tid, a0, a1, a2);

    float acc[2][8][4];

    const int arow = wm * 32 + (lane & 7) + ((lane >> 3) & 1) * 8;
    const int akc  = (lane >> 4) & 1;
    const int brow = wn * 64 + (lane & 7) + ((lane >> 4) & 1) * 8;
    const int bkc  = (lane >> 3) & 1;

#pragma unroll
    for (int c = 0; c < 4; c++) {
        if (c < 3) asm volatile("cp.async.wait_group 1;" ::: "memory");
        else       asm volatile("cp.async.wait_group 0;" ::: "memory");
        __syncthreads();   // single barrier per chunk (3-buffer rotation)
        if (c == 0) {
            const float* sbias = reinterpret_cast<const float*>(smem + SG_BIAS);
#pragma unroll
            for (int nt = 0; nt < 8; nt++) {
                int cl = wn * 64 + nt * 8 + (lane & 3) * 2;
                float b0 = sbias[cl], b1 = sbias[cl + 1];
#pragma unroll
                for (int mt = 0; mt < 2; mt++) {
                    acc[mt][nt][0] = b0; acc[mt][nt][1] = b1;
                    acc[mt][nt][2] = b0; acc[mt][nt][3] = b1;
                }
            }
        }
        // prefetch chunk c+2 into buffer (c+2)%3 — flies under this chunk's HMMAs
        if (c < 2) sg_issue_chunk(sb, (c + 2) % 3, c + 2, tid, a0, a1, a2);

        const uint32_t bb = sb + (c % 3) * SGB;
#pragma unroll
        for (int ks = 0; ks < 2; ks++) {
            uint32_t ahi[2][4], alo[2][4], bhi[8][2];
#pragma unroll
            for (int mt = 0; mt < 2; mt++) {
                int r = arow + mt * 16;
                int sw = (ks * 2 + akc) ^ ((r >> 1) & 3);
                ldsm4(ahi[mt], bb + 0    + r * 64 + sw * 16);
                ldsm4(alo[mt], bb + 8192 + r * 64 + sw * 16);
            }
#pragma unroll
            for (int np = 0; np < 4; np++) {
                int r = brow + np * 16;
                int sw = (ks * 2 + bkc) ^ ((r >> 1) & 3);
                uint32_t t[4];
                ldsm4(t, bb + 16384 + r * 64 + sw * 16);
                bhi[np*2][0] = t[0]; bhi[np*2][1] = t[1];
                bhi[np*2+1][0] = t[2]; bhi[np*2+1][1] = t[3];
            }
            // 2 term passes, 16 independent HMMAs each
#pragma unroll
            for (int mt = 0; mt < 2; mt++)
#pragma unroll
                for (int j = 0; j < 8; j++)
                    mma_f16(acc[mt][j], ahi[mt], bhi[j]);
#pragma unroll
            for (int mt = 0; mt < 2; mt++)
#pragma unroll
                for (int j = 0; j < 8; j++)
                    mma_f16(acc[mt][j], alo[mt], bhi[j]);
        }
    }

    // epilogue: f32 tanh sigmoid + streaming stores (bias already folded in)
#pragma unroll
    for (int mt = 0; mt < 2; mt++) {
        int rg = row0 + wm * 32 + mt * 16 + (lane >> 2);
#pragma unroll
        for (int nt = 0; nt < 8; nt++) {
            int cl = wn * 64 + nt * 8 + (lane & 3) * 2;
            int cg = col0 + cl;
            if (cg >= Nw) continue;
            const float* a = acc[mt][nt];
            float s0 = fast_sigmoid(a[0]);
            float s1 = fast_sigmoid(a[1]);
            float s2 = fast_sigmoid(a[2]);
            float s3 = fast_sigmoid(a[3]);
            if (rg < M)
                stg_cs_v2(out + (size_t)rg * Nw + cg, s0, s1);
            if (rg + 8 < M)
                stg_cs_v2(out + (size_t)(rg + 8) * Nw + cg, s2, s3);
        }
    }
}

// ---------------- launch ----------------
extern "C" void kernel_launch(void* const* d_in, const int* in_sizes, int n_in,
                              void* d_out, int out_size)
{
    const float* x   = (const float*)d_in[0];
    const int*   ei  = (const int*)d_in[1];   // int32 on device (JAX x64 disabled)
    const float* We1 = (const float*)d_in[2];
    const float* be1 = (const float*)d_in[3];
    const float* We2 = (const float*)d_in[4];
    const float* be2 = (const float*)d_in[5];
    const float* Wd1 = (const float*)d_in[6];
    const float* bd1 = (const float*)d_in[7];
    const float* Wd2 = (const float*)d_in[8];
    const float* bd2 = (const float*)d_in[9];
    const float* Wl  = (const float*)d_in[10];
    const float* bl  = (const float*)d_in[11];
    const float* Wf  = (const float*)d_in[12];
    const float* bf  = (const float*)d_in[13];

    const int E = in_sizes[1] / 2;     // edge_index is [2, E]
    const int N = in_sizes[13];        // bf: [N]
    const int F = in_sizes[0] / N;     // x: [N, F]
    const int H = in_sizes[3];         // be1: [H]

    const int* srcp = ei;
    const int* dstp = ei + E;

    float* struct_out = (float*)d_out;                       // [N, N]
    float* xhat_out   = struct_out + (size_t)N * N;          // [N, F]
    float* z_out      = xhat_out + (size_t)N * F;            // [N, H]

    const int tb = 256;
    const bool tc = (H == 128);

    dim3 thr(256);
    auto grid4 = [](int M, int Nc) { return dim3((Nc + BN - 1) / BN, (M + 63) / 64); };
    auto grid8 = [](int M, int Nc) { return dim3((Nc + BN - 1) / BN, (M + 127) / 128); };
    int gb128 = (N * 32 + 255) / 256;       // 1 warp / node  (W = 128)
    int gb512 = (N * 4 * 32 + 255) / 256;   // 4 warps / node (W = 512)

    // CSR (deg/dis) build + struct GEMM prep
    zero_kernel<<<(N + tb - 1) / tb, tb>>>(N);
    if (tc) {
        cudaFuncSetAttribute(struct_gemm_mma, cudaFuncAttributeMaxDynamicSharedMemorySize, SG_SMEM);
        transb_kernel<<<(APAD_ROWS + 63) / 64, 256>>>(Wf, N);
        ztail_kernel<<<((APAD_ROWS - N) * 128 + tb - 1) / tb, tb>>>(N);
    }
    hist_kernel<<<(E + tb - 1) / tb, tb>>>(dstp, E);
    scan_kernel<<<1, 256>>>(N, E);
    fill_kernel<<<(E + tb - 1) / tb, tb>>>(srcp, dstp, E);

    // conv1: x[N,F] @ We1 -> g_tmp -> gather -> g_h1
    gemm_kernel<0, false, 4, false><<<grid4(N, H), thr>>>(x, 0, We1, nullptr, nullptr, 1, N, F, H);
    gather_kernel<0><<<gb128, 256>>>(be1, nullptr, 2, 1, N, H, 0);
    // conv2: g_h1 @ We2 -> g_tmp -> gather -> z (output)
    gemm_kernel<0, false, 4, false><<<grid4(N, H), thr>>>(nullptr, 2, We2, nullptr, nullptr, 1, N, H, H);
    gather_kernel<0><<<gb128, 256>>>(be2, z_out, 0, 1, N, H, 0);
    // conv3: z @ Wd1 -> g_tmp -> gather -> g_d1 (pre-scaled by dis for commuted conv4)
    gemm_kernel<0, false, 4, false><<<grid4(N, H), thr>>>(z_out, 0, Wd1, nullptr, nullptr, 1, N, H, H);

    if (tc) {
        gather_kernel<1><<<gb128, 256>>>(bd1, nullptr, 3, 1, N, H, 0);
        // conv4 (commuted): pre-aggregate d1 (128-wide), then GEMM with fused relu+bias
        gather_kernel<2><<<gb128, 256>>>(nullptr, nullptr, 2, 3, N, H, 0);   // g_d1 -> g_h1
        gemm_kernel<1, false, 4, false><<<grid4(N, F), thr>>>(nullptr, 2, Wd2, bd2, xhat_out, 0, N, H, F);
        // hmid = relu((x_hat^2) @ Wl + bl) -> fp16 hi/lo directly (g_ahi/g_alo)
        gemm_kernel<1, true, 4, true><<<grid4(N, H), thr>>>(xhat_out, 0, Wl, bl, nullptr, 0, N, F, H);
        // struct = sigmoid(hmid @ Wf + bf) via tensor cores (fp16 2-term split)
        dim3 gs((N + 127) / 128, (N + 127) / 128);
        struct_gemm_mma<<<gs, thr, SG_SMEM>>>(bf, struct_out, N, N);
    } else {
        // fallback: pure fp32 path, original conv4 order
        gather_kernel<0><<<gb128, 256>>>(bd1, nullptr, 3, 1, N, H, 0);
        gemm_kernel<0, false, 8, false><<<grid8(N, F), thr>>>(nullptr, 3, Wd2, nullptr, nullptr, 1, N, H, F);
        gather_kernel<0><<<gb512, 256>>>(bd2, xhat_out, 0, 1, N, F, 2);
        gemm_kernel<1, true, 4, false><<<grid4(N, H), thr>>>(xhat_out, 0, Wl, bl, nullptr, 1, N, F, H);
        gemm_kernel<2, false, 8, false><<<grid8(N, N), thr>>>(nullptr, 1, Wf, bf, struct_out, 0, N, H, N);
    }
}